// round 4
// baseline (speedup 1.0000x reference)
#include <cuda_runtime.h>
#include <math.h>
#include <stdint.h>

#define NV 10000
#define EV 160000
#define CV 512
#define HV 4
#define RV 8
#define LLV 2
#define EDV 768
#define OV 128

// ---------------- scratch (device globals; no cudaMalloc allowed) ----------------
__device__ float g_xw[(size_t)NV * RV * CV];     // 164 MB  [n][r][c]
__device__ float g_xA[NV * CV];
__device__ float g_xB[NV * CV];
__device__ float g_h0[NV * CV];
__device__ float g_h1[NV * 2 * CV];
__device__ float g_xt[NV * CV];                  // tf32-rounded activations
__device__ float g_h0t[NV * CV];
__device__ float g_Wt[(size_t)LLV * RV * CV * CV];  // tf32-rounded weights
__device__ float g_f1t[CV * 2 * CV];
__device__ float g_f2t[2 * CV * CV];
__device__ float g_Wqk[LLV * CV * 64];           // [l][c][ 0..31: q(r*4+h) | 32..63: k ]
__device__ float g_QK[NV * 64];
__device__ float g_P[EDV * LLV * HV];
__device__ float g_ae[(size_t)EV * LLV * HV];
__device__ float g_alpha[EV * HV];
__device__ unsigned g_maxu[NV * HV];
__device__ float g_den[NV * HV];
__device__ int g_src[EV], g_dst[EV], g_typ[EV];
__device__ int g_cnt[NV], g_off[NV + 1], g_cur[NV];
__device__ int g_perm[EV];
__device__ int g_flags[2];

// ---------------- helpers ----------------
__device__ __forceinline__ float warp_red(float v) {
#pragma unroll
    for (int s = 16; s; s >>= 1) v += __shfl_down_sync(0xffffffffu, v, s);
    return v;
}
__device__ __forceinline__ unsigned fenc(float f) {
    unsigned b = __float_as_uint(f);
    return (b & 0x80000000u) ? ~b : (b | 0x80000000u);
}
__device__ __forceinline__ float fdec(unsigned u) {
    return __uint_as_float((u & 0x80000000u) ? (u ^ 0x80000000u) : ~u);
}
__device__ __forceinline__ float tf32r(float f) {
    unsigned u;
    asm("cvt.rna.tf32.f32 %0, %1;" : "=r"(u) : "f"(f));
    return __uint_as_float(u);
}
__device__ __forceinline__ void mma_tf32(float* d, const unsigned* a, const unsigned* b) {
    asm volatile(
        "mma.sync.aligned.m16n8k8.row.col.f32.tf32.tf32.f32 "
        "{%0,%1,%2,%3}, {%4,%5,%6,%7}, {%8,%9}, {%0,%1,%2,%3};"
        : "+f"(d[0]), "+f"(d[1]), "+f"(d[2]), "+f"(d[3])
        : "r"(a[0]), "r"(a[1]), "r"(a[2]), "r"(a[3]), "r"(b[0]), "r"(b[1]));
}
__device__ __forceinline__ void cp16(uint32_t dst, const void* src, bool p) {
    int sz = p ? 16 : 0;
    asm volatile("cp.async.cg.shared.global [%0], [%1], 16, %2;\n"
                 :: "r"(dst), "l"(src), "r"(sz));
}

// ---------------- edge index dtype detection + conversion ----------------
__global__ void detect_kernel(const int* __restrict__ a, const int* __restrict__ b) {
    __shared__ int nz[2];
    if (threadIdx.x < 2) nz[threadIdx.x] = 0;
    __syncthreads();
    int i = threadIdx.x;
    if (a[2 * i + 1] != 0) atomicAdd(&nz[0], 1);
    if (b[2 * i + 1] != 0) atomicAdd(&nz[1], 1);
    __syncthreads();
    if (threadIdx.x == 0) { g_flags[0] = (nz[0] == 0); g_flags[1] = (nz[1] == 0); }
}

__global__ void convert_kernel(const void* __restrict__ ei, const void* __restrict__ et) {
    int e = blockIdx.x * blockDim.x + threadIdx.x;
    if (e >= EV) return;
    int f0 = g_flags[0], f1 = g_flags[1];
    int s, d, t;
    if (f0) {
        const long long* a = (const long long*)ei;
        s = (int)a[e]; d = (int)a[EV + e];
    } else {
        const int* a = (const int*)ei;
        s = a[e]; d = a[EV + e];
    }
    if (f1) t = (int)((const long long*)et)[e];
    else    t = ((const int*)et)[e];
    g_src[e] = s; g_dst[e] = d; g_typ[e] = t;
}

// ---------------- CSR build ----------------
__global__ void reset_cnt_kernel() {
    int i = blockIdx.x * blockDim.x + threadIdx.x;
    if (i < NV) g_cnt[i] = 0;
}
__global__ void hist_kernel() {
    int e = blockIdx.x * blockDim.x + threadIdx.x;
    if (e < EV) atomicAdd(&g_cnt[g_dst[e]], 1);
}
__global__ void scan_kernel() {
    __shared__ int sh[1024];
    __shared__ int carry;
    int t = threadIdx.x;
    if (t == 0) carry = 0;
    __syncthreads();
    for (int base = 0; base < NV; base += 1024) {
        int i = base + t;
        int v = (i < NV) ? g_cnt[i] : 0;
        sh[t] = v;
        __syncthreads();
        for (int s = 1; s < 1024; s <<= 1) {
            int add = (t >= s) ? sh[t - s] : 0;
            __syncthreads();
            sh[t] += add;
            __syncthreads();
        }
        int excl = sh[t] - v + carry;
        if (i < NV) { g_off[i] = excl; g_cur[i] = excl; }
        int tot = sh[1023];
        __syncthreads();
        if (t == 0) carry += tot;
        __syncthreads();
    }
    if (threadIdx.x == 0) g_off[NV] = carry;
}
__global__ void scatter_kernel() {
    int e = blockIdx.x * blockDim.x + threadIdx.x;
    if (e >= EV) return;
    int d = g_dst[e];
    int p = atomicAdd(&g_cur[d], 1);
    g_perm[p] = e;
}

// ---------------- elementwise tf32 rounding ----------------
__global__ void cvt_kernel(const float* __restrict__ in, float* __restrict__ out, int n4) {
    int i = blockIdx.x * blockDim.x + threadIdx.x;
    if (i >= n4) return;
    float4 v = ((const float4*)in)[i];
    v.x = tf32r(v.x); v.y = tf32r(v.y); v.z = tf32r(v.z); v.w = tf32r(v.w);
    ((float4*)out)[i] = v;
}

// ---------------- Wqk[l][c][*] = [ W[l,r]@q | W[l,r]@k ]  (tf32-rounded) ----------------
__global__ void wqk_kernel(const float* __restrict__ W, const float* __restrict__ q,
                           const float* __restrict__ k) {
    int l = blockIdx.x >> 3, r = blockIdx.x & 7;
    __shared__ float sq[CV * HV], sk[CV * HV];
    for (int i = threadIdx.x; i < CV * HV; i += 256) {
        sq[i] = q[(long)l * CV * HV + i];
        sk[i] = k[(long)l * CV * HV + i];
    }
    __syncthreads();
#pragma unroll
    for (int rep = 0; rep < 2; rep++) {
        int cc = threadIdx.x + rep * 256;
        const float* wrow = W + (((long)l * RV + r) * CV + cc) * CV;
        float aq[HV] = {0, 0, 0, 0}, ak[HV] = {0, 0, 0, 0};
        for (int d = 0; d < CV; d += 4) {
            float4 w4 = *(const float4*)(wrow + d);
            const float* wv = &w4.x;
#pragma unroll
            for (int u = 0; u < 4; u++) {
                float w = wv[u];
                const float* qd = sq + (d + u) * HV;
                const float* kd = sk + (d + u) * HV;
                aq[0] = fmaf(w, qd[0], aq[0]); aq[1] = fmaf(w, qd[1], aq[1]);
                aq[2] = fmaf(w, qd[2], aq[2]); aq[3] = fmaf(w, qd[3], aq[3]);
                ak[0] = fmaf(w, kd[0], ak[0]); ak[1] = fmaf(w, kd[1], ak[1]);
                ak[2] = fmaf(w, kd[2], ak[2]); ak[3] = fmaf(w, kd[3], ak[3]);
            }
        }
        float* o = g_Wqk + ((long)l * CV + cc) * 64;
#pragma unroll
        for (int h = 0; h < HV; h++) {
            o[r * 4 + h] = tf32r(aq[h]);
            o[32 + r * 4 + h] = tf32r(ak[h]);
        }
    }
}

// ---------------- TF32 GEMM, cp.async double-buffered, 4 warps 64x64 ----------------
// C[m, n (+z*cz)] = A[m,:] @ B(z)[:,n]; EPI: 0 none, 1 bias+relu(+tf32 round), 2 bias+residual
template <int EPI>
__global__ __launch_bounds__(128)
void tgemm_k(const float* __restrict__ A, const float* __restrict__ B,
             float* __restrict__ C, int M, int Nc, int K,
             int lda, int ldb, int ldc, long bz, long cz,
             const float* __restrict__ bias, const float* __restrict__ res) {
    B += (long)blockIdx.z * bz;
    C += (long)blockIdx.z * cz;
    __shared__ __align__(16) float As[2][128][20];   // [m][k], stride 20 conflict-free
    __shared__ __align__(16) float Bs[2][16][136];   // [k][n], stride 136

    const int tid = threadIdx.x;
    const int warp = tid >> 5, lane = tid & 31;
    const int wm = warp >> 1, wn = warp & 1;          // 2x2 warps, 64x64 each
    const int g = lane >> 2, c = lane & 3;
    const int m0 = blockIdx.y * 128, n0 = blockIdx.x * 128;

    const int arow = tid >> 2, ac4 = tid & 3;         // + i*32 rows, 4 iters
    const int brow = tid >> 5, bcol = (tid & 31) * 4; // + i*4 rows, 4 iters

    uint32_t sA = (uint32_t)__cvta_generic_to_shared(&As[0][0][0]);
    uint32_t sB = (uint32_t)__cvta_generic_to_shared(&Bs[0][0][0]);

    float acc[4][8][4];
#pragma unroll
    for (int i = 0; i < 4; i++)
#pragma unroll
        for (int j = 0; j < 8; j++)
#pragma unroll
            for (int qq = 0; qq < 4; qq++) acc[i][j][qq] = 0.f;

    const int KT = K >> 4;

#define LOAD_STAGE(s, kt)                                                              \
    {                                                                                  \
        _Pragma("unroll")                                                              \
        for (int i = 0; i < 4; i++) {                                                  \
            int r = arow + i * 32;                                                     \
            bool p = (m0 + r) < M;                                                     \
            const float* gp = A + (long)(m0 + r) * lda + (kt) * 16 + ac4 * 4;          \
            cp16(sA + (((s) * 128 + r) * 20 + ac4 * 4) * 4, gp, p);                    \
        }                                                                              \
        _Pragma("unroll")                                                              \
        for (int i = 0; i < 4; i++) {                                                  \
            int r = brow + i * 4;                                                      \
            bool p = (n0 + bcol) < Nc;                                                 \
            const float* gp = B + (long)((kt) * 16 + r) * ldb + n0 + bcol;             \
            cp16(sB + (((s) * 16 + r) * 136 + bcol) * 4, gp, p);                       \
        }                                                                              \
        asm volatile("cp.async.commit_group;\n");                                      \
    }

    LOAD_STAGE(0, 0);

    for (int kt = 0; kt < KT; kt++) {
        asm volatile("cp.async.wait_group 0;\n");
        __syncthreads();
        if (kt + 1 < KT) LOAD_STAGE((kt + 1) & 1, kt + 1);
        int buf = kt & 1;
#pragma unroll
        for (int ks = 0; ks < 2; ks++) {
            int k0 = ks * 8;
            unsigned af[4][4], bf[8][2];
#pragma unroll
            for (int mt = 0; mt < 4; mt++) {
                int mr = wm * 64 + mt * 16;
                af[mt][0] = __float_as_uint(As[buf][mr + g][k0 + c]);
                af[mt][1] = __float_as_uint(As[buf][mr + g + 8][k0 + c]);
                af[mt][2] = __float_as_uint(As[buf][mr + g][k0 + c + 4]);
                af[mt][3] = __float_as_uint(As[buf][mr + g + 8][k0 + c + 4]);
            }
#pragma unroll
            for (int nt = 0; nt < 8; nt++) {
                int nc = wn * 64 + nt * 8;
                bf[nt][0] = __float_as_uint(Bs[buf][k0 + c][nc + g]);
                bf[nt][1] = __float_as_uint(Bs[buf][k0 + c + 4][nc + g]);
            }
#pragma unroll
            for (int mt = 0; mt < 4; mt++)
#pragma unroll
                for (int nt = 0; nt < 8; nt++)
                    mma_tf32(acc[mt][nt], af[mt], bf[nt]);
        }
    }
#undef LOAD_STAGE

    // epilogue
#pragma unroll
    for (int mt = 0; mt < 4; mt++) {
#pragma unroll
        for (int half = 0; half < 2; half++) {
            int m = m0 + wm * 64 + mt * 16 + g + half * 8;
            if (m >= M) continue;
#pragma unroll
            for (int nt = 0; nt < 8; nt++) {
                int n = n0 + wn * 64 + nt * 8 + 2 * c;
                if (n >= Nc) continue;
                float v0 = acc[mt][nt][half * 2 + 0];
                float v1 = acc[mt][nt][half * 2 + 1];
                if (EPI == 1) {
                    v0 = tf32r(fmaxf(v0 + bias[n], 0.f));
                    v1 = tf32r(fmaxf(v1 + bias[n + 1], 0.f));
                } else if (EPI == 2) {
                    v0 = v0 + bias[n] + res[(long)m * Nc + n];
                    v1 = v1 + bias[n + 1] + res[(long)m * Nc + n + 1];
                }
                *(float2*)(C + (long)m * ldc + n) = make_float2(v0, v1);
            }
        }
    }
}

// ---------------- P = We @ e, both layers ----------------
__global__ void p_kernel(const float* __restrict__ we, const float* __restrict__ ev) {
    int j = blockIdx.x * 8 + (threadIdx.x >> 5);
    int lane = threadIdx.x & 31;
    float a[8];
#pragma unroll
    for (int u = 0; u < 8; u++) a[u] = 0.f;
#pragma unroll
    for (int jj = 0; jj < 16; jj++) {
        int c = lane + 32 * jj;
        float w0 = we[(long)j * CV + c];
        float w1 = we[(long)EDV * CV + (long)j * CV + c];
        float4 e0 = *(const float4*)(ev + c * HV);
        float4 e1 = *(const float4*)(ev + CV * HV + c * HV);
        a[0] = fmaf(w0, e0.x, a[0]); a[1] = fmaf(w0, e0.y, a[1]);
        a[2] = fmaf(w0, e0.z, a[2]); a[3] = fmaf(w0, e0.w, a[3]);
        a[4] = fmaf(w1, e1.x, a[4]); a[5] = fmaf(w1, e1.y, a[5]);
        a[6] = fmaf(w1, e1.z, a[6]); a[7] = fmaf(w1, e1.w, a[7]);
    }
#pragma unroll
    for (int u = 0; u < 8; u++) a[u] = warp_red(a[u]);
    if (lane == 0) {
        *(float4*)(g_P + j * 8) = make_float4(a[0], a[1], a[2], a[3]);
        *(float4*)(g_P + j * 8 + 4) = make_float4(a[4], a[5], a[6], a[7]);
    }
}

// ---------------- ae = eattr @ P, both layers ----------------
__global__ void ae_kernel(const float* __restrict__ eattr) {
    int e = blockIdx.x * 8 + (threadIdx.x >> 5);
    int lane = threadIdx.x & 31;
    float a[8];
#pragma unroll
    for (int u = 0; u < 8; u++) a[u] = 0.f;
#pragma unroll
    for (int jj = 0; jj < 24; jj++) {
        int j = lane + 32 * jj;
        float v = eattr[(long)e * EDV + j];
        float4 p0 = *(const float4*)(g_P + j * 8);
        float4 p1 = *(const float4*)(g_P + j * 8 + 4);
        a[0] = fmaf(v, p0.x, a[0]); a[1] = fmaf(v, p0.y, a[1]);
        a[2] = fmaf(v, p0.z, a[2]); a[3] = fmaf(v, p0.w, a[3]);
        a[4] = fmaf(v, p1.x, a[4]); a[5] = fmaf(v, p1.y, a[5]);
        a[6] = fmaf(v, p1.z, a[6]); a[7] = fmaf(v, p1.w, a[7]);
    }
#pragma unroll
    for (int u = 0; u < 8; u++) a[u] = warp_red(a[u]);
    if (lane == 0) {
        *(float4*)(g_ae + (long)e * 8) = make_float4(a[0], a[1], a[2], a[3]);
        *(float4*)(g_ae + (long)e * 8 + 4) = make_float4(a[4], a[5], a[6], a[7]);
    }
}

// ---------------- per-layer reset of softmax state ----------------
__global__ void reset_nodes_kernel() {
    int i = blockIdx.x * blockDim.x + threadIdx.x;
    if (i < NV * HV) { g_maxu[i] = 0u; g_den[i] = 0.f; }
}

// ---------------- attention logits + leaky_relu + segment max ----------------
__global__ void logits_kernel(int l) {
    int e = blockIdx.x * blockDim.x + threadIdx.x;
    if (e >= EV) return;
    int dst = g_dst[e], src = g_src[e], t = g_typ[e];
    float4 ae = *(const float4*)(g_ae + (long)e * (LLV * HV) + l * HV);
    float4 qv = *(const float4*)(g_QK + (long)dst * 64 + t * 4);
    float4 kv = *(const float4*)(g_QK + (long)src * 64 + 32 + t * 4);
    float4 a;
    a.x = qv.x + kv.x + ae.x; a.x = a.x > 0.f ? a.x : 0.2f * a.x;
    a.y = qv.y + kv.y + ae.y; a.y = a.y > 0.f ? a.y : 0.2f * a.y;
    a.z = qv.z + kv.z + ae.z; a.z = a.z > 0.f ? a.z : 0.2f * a.z;
    a.w = qv.w + kv.w + ae.w; a.w = a.w > 0.f ? a.w : 0.2f * a.w;
    *(float4*)(g_alpha + (long)e * HV) = a;
    atomicMax(&g_maxu[dst * HV + 0], fenc(a.x));
    atomicMax(&g_maxu[dst * HV + 1], fenc(a.y));
    atomicMax(&g_maxu[dst * HV + 2], fenc(a.z));
    atomicMax(&g_maxu[dst * HV + 3], fenc(a.w));
}

// ---------------- exp + segment sum ----------------
__global__ void expsum_kernel() {
    int e = blockIdx.x * blockDim.x + threadIdx.x;
    if (e >= EV) return;
    int dst = g_dst[e];
    float4 a = *(const float4*)(g_alpha + (long)e * HV);
    a.x = expf(a.x - fdec(g_maxu[dst * HV + 0]));
    a.y = expf(a.y - fdec(g_maxu[dst * HV + 1]));
    a.z = expf(a.z - fdec(g_maxu[dst * HV + 2]));
    a.w = expf(a.w - fdec(g_maxu[dst * HV + 3]));
    *(float4*)(g_alpha + (long)e * HV) = a;
    atomicAdd(&g_den[dst * HV + 0], a.x);
    atomicAdd(&g_den[dst * HV + 1], a.y);
    atomicAdd(&g_den[dst * HV + 2], a.z);
    atomicAdd(&g_den[dst * HV + 3], a.w);
}

// ---------------- CSR aggregation (optionally emits tf32-rounded copy) ----------------
__global__ void agg_kernel(const float* __restrict__ xin, float* __restrict__ xout,
                           float* __restrict__ xout_t, const float* __restrict__ bias) {
    int n = blockIdx.x;
    int t = threadIdx.x;
    int h = t >> 5;
    float inv = 1.f / (g_den[n * HV + h] + 1e-16f);
    float4 acc = ((const float4*)bias)[t];
    float4 xr = ((const float4*)(xin + (long)n * CV))[t];
    acc.x += xr.x; acc.y += xr.y; acc.z += xr.z; acc.w += xr.w;
    int b0 = g_off[n], b1 = g_off[n + 1];
    for (int ii = b0; ii < b1; ii++) {
        int e = g_perm[ii];
        float coeff = g_alpha[e * HV + h] * inv;
        const float4* vp = (const float4*)(g_xw + ((long)g_src[e] * RV + g_typ[e]) * CV) + t;
        float4 vv = *vp;
        acc.x = fmaf(coeff, vv.x, acc.x);
        acc.y = fmaf(coeff, vv.y, acc.y);
        acc.z = fmaf(coeff, vv.z, acc.z);
        acc.w = fmaf(coeff, vv.w, acc.w);
    }
    ((float4*)(xout + (long)n * CV))[t] = acc;
    if (xout_t) {
        acc.x = tf32r(acc.x); acc.y = tf32r(acc.y);
        acc.z = tf32r(acc.z); acc.w = tf32r(acc.w);
        ((float4*)(xout_t + (long)n * CV))[t] = acc;
    }
}

// ---------------- layernorm (optionally emits tf32-rounded copy) ----------------
__global__ void ln_kernel(const float* __restrict__ in, const float* __restrict__ addpre,
                          const float* __restrict__ addpost, float* __restrict__ out,
                          float* __restrict__ out_t,
                          const float* __restrict__ gamma, const float* __restrict__ beta) {
    int n = blockIdx.x, t = threadIdx.x;
    int lane = t & 31, w = t >> 5;
    __shared__ float sred[4];
    float4 x = ((const float4*)(in + (long)n * CV))[t];
    if (addpre) {
        float4 a = ((const float4*)(addpre + (long)n * CV))[t];
        x.x += a.x; x.y += a.y; x.z += a.z; x.w += a.w;
    }
    float s = x.x + x.y + x.z + x.w;
    s = warp_red(s);
    if (!lane) sred[w] = s;
    __syncthreads();
    float mean = (sred[0] + sred[1] + sred[2] + sred[3]) * (1.f / CV);
    __syncthreads();
    float dx = x.x - mean, dy = x.y - mean, dz = x.z - mean, dw = x.w - mean;
    float ss = dx * dx + dy * dy + dz * dz + dw * dw;
    ss = warp_red(ss);
    if (!lane) sred[w] = ss;
    __syncthreads();
    float var = (sred[0] + sred[1] + sred[2] + sred[3]) * (1.f / CV);
    float rstd = rsqrtf(var + 1e-5f);
    float4 g = ((const float4*)gamma)[t];
    float4 b = ((const float4*)beta)[t];
    float4 o;
    o.x = g.x * dx * rstd + b.x;
    o.y = g.y * dy * rstd + b.y;
    o.z = g.z * dz * rstd + b.z;
    o.w = g.w * dw * rstd + b.w;
    if (addpost) {
        float4 p = ((const float4*)(addpost + (long)n * CV))[t];
        o.x += p.x; o.y += p.y; o.z += p.z; o.w += p.w;
    }
    ((float4*)(out + (long)n * CV))[t] = o;
    if (out_t) {
        float4 ot;
        ot.x = tf32r(o.x); ot.y = tf32r(o.y); ot.z = tf32r(o.z); ot.w = tf32r(o.w);
        ((float4*)(out_t + (long)n * CV))[t] = ot;
    }
}

// ---------------- launcher ----------------
extern "C" void kernel_launch(void* const* d_in, const int* in_sizes, int n_in,
                              void* d_out, int out_size) {
    const float* x   = (const float*)d_in[0];
    const void*  ei  = d_in[1];
    const void*  et  = d_in[2];
    const float* eattr = (const float*)d_in[3];
    const float* W   = (const float*)d_in[4];
    const float* qm  = (const float*)d_in[5];
    const float* km  = (const float*)d_in[6];
    const float* em  = (const float*)d_in[7];
    const float* we  = (const float*)d_in[8];
    const float* cb  = (const float*)d_in[9];
    const float* lg  = (const float*)d_in[10];
    const float* lb  = (const float*)d_in[11];
    const float* f1w = (const float*)d_in[12];
    const float* f1b = (const float*)d_in[13];
    const float* f2w = (const float*)d_in[14];
    const float* f2b = (const float*)d_in[15];
    float* out = (float*)d_out;

    float *pxw, *pxA, *pxB, *ph0, *ph1, *pxt, *ph0t, *pWt, *pf1t, *pf2t, *pWqk, *pQK;
    cudaGetSymbolAddress((void**)&pxw, g_xw);
    cudaGetSymbolAddress((void**)&pxA, g_xA);
    cudaGetSymbolAddress((void**)&pxB, g_xB);
    cudaGetSymbolAddress((void**)&ph0, g_h0);
    cudaGetSymbolAddress((void**)&ph1, g_h1);
    cudaGetSymbolAddress((void**)&pxt, g_xt);
    cudaGetSymbolAddress((void**)&ph0t, g_h0t);
    cudaGetSymbolAddress((void**)&pWt, g_Wt);
    cudaGetSymbolAddress((void**)&pf1t, g_f1t);
    cudaGetSymbolAddress((void**)&pf2t, g_f2t);
    cudaGetSymbolAddress((void**)&pWqk, g_Wqk);
    cudaGetSymbolAddress((void**)&pQK, g_QK);

    const int TB = 256;
    const int EB = (EV + TB - 1) / TB;
    const int MT = (NV + 127) / 128;

    detect_kernel<<<1, 256>>>((const int*)ei, (const int*)et);
    convert_kernel<<<EB, TB>>>(ei, et);
    reset_cnt_kernel<<<(NV + TB - 1) / TB, TB>>>();
    hist_kernel<<<EB, TB>>>();
    scan_kernel<<<1, 1024>>>();
    scatter_kernel<<<EB, TB>>>();

    // edge-attr projections for BOTH layers in one eattr pass
    p_kernel<<<EDV / 8, 256>>>(we, em);
    ae_kernel<<<EV / 8, 256>>>(eattr);

    // precompute fused QK weights and tf32-rounded weight copies
    wqk_kernel<<<LLV * RV, 256>>>(W, qm, km);
    {
        int n4;
        n4 = LLV * RV * CV * CV / 4;
        cvt_kernel<<<(n4 + TB - 1) / TB, TB>>>(W, pWt, n4);
        n4 = CV * 2 * CV / 4;
        cvt_kernel<<<(n4 + TB - 1) / TB, TB>>>(f1w, pf1t, n4);
        cvt_kernel<<<(n4 + TB - 1) / TB, TB>>>(f2w, pf2t, n4);
    }

    // tf32-rounded copy of layer-0 activations
    cvt_kernel<<<(NV * CV / 4 + TB - 1) / TB, TB>>>(x, pxt, NV * CV / 4);

    for (int l = 0; l < LLV; l++) {
        const float* xin = (l == 0) ? x : pxB;      // raw residual input
        float* xout = (l == 0) ? pxB : pxA;
        float* xout_t = (l == 0) ? pxt : nullptr;   // rounded copy feeds layer-1 GEMMs

        // xw[n,r,:] = xt @ Wt[l,r]
        dim3 g1(CV / 128, MT, RV);
        tgemm_k<0><<<g1, 128>>>(pxt, pWt + (long)l * RV * CV * CV, pxw,
                                NV, CV, CV, CV, CV, RV * CV,
                                (long)CV * CV, (long)CV, nullptr, nullptr);

        // QK[n, 0..63] = xt @ Wqk[l]
        dim3 gq(1, MT, 1);
        tgemm_k<0><<<gq, 128>>>(pxt, pWqk + (long)l * CV * 64, pQK,
                                NV, 64, CV, CV, 64, 64, 0, 0, nullptr, nullptr);

        reset_nodes_kernel<<<(NV * HV + TB - 1) / TB, TB>>>();
        logits_kernel<<<EB, TB>>>(l);
        expsum_kernel<<<EB, TB>>>();
        agg_kernel<<<NV, 128>>>(xin, xout, xout_t, cb + l * CV);
    }

    // h0 = LN(xA + enc_emb), also emit tf32 copy
    ln_kernel<<<NV, 128>>>(pxA, x, nullptr, ph0, ph0t, lg, lb);
    // h1 = tf32(relu(h0t @ f1t + b1))
    {
        dim3 g2(2 * CV / 128, MT, 1);
        tgemm_k<1><<<g2, 128>>>(ph0t, pf1t, ph1, NV, 2 * CV, CV,
                                CV, 2 * CV, 2 * CV, 0, 0, f1b, nullptr);
    }
    // h2 = h1 @ f2t + b2 + h0  (into pxB)
    {
        dim3 g3(CV / 128, MT, 1);
        tgemm_k<2><<<g3, 128>>>(ph1, pf2t, pxB, NV, CV, 2 * CV,
                                2 * CV, CV, CV, 0, 0, f2b, ph0);
    }
    // out = LN(h2) + enc_emb
    ln_kernel<<<NV, 128>>>(pxB, nullptr, x, out, nullptr, lg, lb);
}

// round 7
// speedup vs baseline: 1.3496x; 1.3496x over previous
#include <cuda_runtime.h>
#include <cuda_fp16.h>
#include <math.h>
#include <stdint.h>

#define NV 10000
#define EV 160000
#define CV 512
#define HV 4
#define RV 8
#define LLV 2
#define EDV 768
#define OV 128

// ---------------- scratch (device globals; no cudaMalloc allowed) ----------------
__device__ float g_xw[(size_t)NV * RV * CV];     // [n][r][c]
__device__ float g_xA[NV * CV];
__device__ float g_xB[NV * CV];
__device__ float g_h0[NV * CV];
__device__ __half g_xh[NV * CV];                 // fp16 activations (GEMM A operand)
__device__ __half g_h0h[NV * CV];
__device__ __half g_h1h[NV * 2 * CV];
__device__ __half g_Wth[(size_t)LLV * RV * CV * CV]; // fp16 transposed weights [l][r][n][k]
__device__ __half g_f1th[2 * CV * CV];               // [n=1024][k=512]
__device__ __half g_f2th[CV * 2 * CV];               // [n=512][k=1024]
__device__ __half g_Wqkh[LLV * 64 * CV];             // [l][n=64][k=512]
__device__ float g_QK[NV * 64];
__device__ float g_P[EDV * LLV * HV];
__device__ float g_ae[(size_t)EV * LLV * HV];
__device__ float g_alpha[EV * HV];
__device__ unsigned g_maxu[NV * HV];
__device__ float g_den[NV * HV];
__device__ int g_src[EV], g_dst[EV], g_typ[EV];
__device__ int g_cnt[NV], g_off[NV + 1], g_cur[NV];
__device__ int g_perm[EV];
__device__ int g_flags[2];

// ---------------- helpers ----------------
__device__ __forceinline__ float warp_red(float v) {
#pragma unroll
    for (int s = 16; s; s >>= 1) v += __shfl_down_sync(0xffffffffu, v, s);
    return v;
}
__device__ __forceinline__ unsigned fenc(float f) {
    unsigned b = __float_as_uint(f);
    return (b & 0x80000000u) ? ~b : (b | 0x80000000u);
}
__device__ __forceinline__ float fdec(unsigned u) {
    return __uint_as_float((u & 0x80000000u) ? (u ^ 0x80000000u) : ~u);
}
__device__ __forceinline__ void mma_f16(float* d, const unsigned* a, const unsigned* b) {
    asm volatile(
        "mma.sync.aligned.m16n8k16.row.col.f32.f16.f16.f32 "
        "{%0,%1,%2,%3}, {%4,%5,%6,%7}, {%8,%9}, {%0,%1,%2,%3};"
        : "+f"(d[0]), "+f"(d[1]), "+f"(d[2]), "+f"(d[3])
        : "r"(a[0]), "r"(a[1]), "r"(a[2]), "r"(a[3]), "r"(b[0]), "r"(b[1]));
}
__device__ __forceinline__ void cp16(uint32_t dst, const void* src, bool p) {
    int sz = p ? 16 : 0;
    asm volatile("cp.async.cg.shared.global [%0], [%1], 16, %2;\n"
                 :: "r"(dst), "l"(src), "r"(sz));
}

// ---------------- edge index dtype detection + conversion ----------------
__global__ void detect_kernel(const int* __restrict__ a, const int* __restrict__ b) {
    __shared__ int nz[2];
    if (threadIdx.x < 2) nz[threadIdx.x] = 0;
    __syncthreads();
    int i = threadIdx.x;
    if (a[2 * i + 1] != 0) atomicAdd(&nz[0], 1);
    if (b[2 * i + 1] != 0) atomicAdd(&nz[1], 1);
    __syncthreads();
    if (threadIdx.x == 0) { g_flags[0] = (nz[0] == 0); g_flags[1] = (nz[1] == 0); }
}

__global__ void convert_kernel(const void* __restrict__ ei, const void* __restrict__ et) {
    int e = blockIdx.x * blockDim.x + threadIdx.x;
    if (e >= EV) return;
    int f0 = g_flags[0], f1 = g_flags[1];
    int s, d, t;
    if (f0) {
        const long long* a = (const long long*)ei;
        s = (int)a[e]; d = (int)a[EV + e];
    } else {
        const int* a = (const int*)ei;
        s = a[e]; d = a[EV + e];
    }
    if (f1) t = (int)((const long long*)et)[e];
    else    t = ((const int*)et)[e];
    g_src[e] = s; g_dst[e] = d; g_typ[e] = t;
}

// ---------------- CSR build ----------------
__global__ void reset_cnt_kernel() {
    int i = blockIdx.x * blockDim.x + threadIdx.x;
    if (i < NV) g_cnt[i] = 0;
}
__global__ void hist_kernel() {
    int e = blockIdx.x * blockDim.x + threadIdx.x;
    if (e < EV) atomicAdd(&g_cnt[g_dst[e]], 1);
}
__global__ void scan_kernel() {
    __shared__ int sh[1024];
    __shared__ int carry;
    int t = threadIdx.x;
    if (t == 0) carry = 0;
    __syncthreads();
    for (int base = 0; base < NV; base += 1024) {
        int i = base + t;
        int v = (i < NV) ? g_cnt[i] : 0;
        sh[t] = v;
        __syncthreads();
        for (int s = 1; s < 1024; s <<= 1) {
            int add = (t >= s) ? sh[t - s] : 0;
            __syncthreads();
            sh[t] += add;
            __syncthreads();
        }
        int excl = sh[t] - v + carry;
        if (i < NV) { g_off[i] = excl; g_cur[i] = excl; }
        int tot = sh[1023];
        __syncthreads();
        if (t == 0) carry += tot;
        __syncthreads();
    }
    if (threadIdx.x == 0) g_off[NV] = carry;
}
__global__ void scatter_kernel() {
    int e = blockIdx.x * blockDim.x + threadIdx.x;
    if (e >= EV) return;
    int d = g_dst[e];
    int p = atomicAdd(&g_cur[d], 1);
    g_perm[p] = e;
}

// ---------------- elementwise fp16 conversion ----------------
__global__ void cvt_half_kernel(const float* __restrict__ in, __half* __restrict__ out, int n4) {
    int i = blockIdx.x * blockDim.x + threadIdx.x;
    if (i >= n4) return;
    float4 v = ((const float4*)in)[i];
    __half2 h0 = __floats2half2_rn(v.x, v.y);
    __half2 h1 = __floats2half2_rn(v.z, v.w);
    ((__half2*)out)[i * 2 + 0] = h0;
    ((__half2*)out)[i * 2 + 1] = h1;
}

// ---------------- transpose + fp16: in [K][N] -> out [N][K], z-batched ----------------
__global__ void trans_cvt_kernel(const float* __restrict__ in, __half* __restrict__ out,
                                 int K, int N) {
    in += (long)blockIdx.z * K * N;
    out += (long)blockIdx.z * K * N;
    __shared__ float tile[32][33];
    int k0 = blockIdx.y * 32, nb = blockIdx.x * 32;
    int tx = threadIdx.x, ty = threadIdx.y;  // 32x8
#pragma unroll
    for (int i = 0; i < 4; i++)
        tile[ty + i * 8][tx] = in[(long)(k0 + ty + i * 8) * N + nb + tx];
    __syncthreads();
#pragma unroll
    for (int i = 0; i < 4; i++)
        out[(long)(nb + ty + i * 8) * K + k0 + tx] = __float2half(tile[tx][ty + i * 8]);
}

// ---------------- Wqkh[l][n][k]: rows 0..31 = W[l,r]@q (n=r*4+h), 32..63 = W[l,r]@k ----------------
__global__ void wqk_kernel(const float* __restrict__ W, const float* __restrict__ q,
                           const float* __restrict__ k) {
    int l = blockIdx.x >> 3, r = blockIdx.x & 7;
    __shared__ float sq[CV * HV], sk[CV * HV];
    for (int i = threadIdx.x; i < CV * HV; i += 256) {
        sq[i] = q[(long)l * CV * HV + i];
        sk[i] = k[(long)l * CV * HV + i];
    }
    __syncthreads();
#pragma unroll
    for (int rep = 0; rep < 2; rep++) {
        int cc = threadIdx.x + rep * 256;
        const float* wrow = W + (((long)l * RV + r) * CV + cc) * CV;
        float aq[HV] = {0, 0, 0, 0}, ak[HV] = {0, 0, 0, 0};
        for (int d = 0; d < CV; d += 4) {
            float4 w4 = *(const float4*)(wrow + d);
            const float* wv = &w4.x;
#pragma unroll
            for (int u = 0; u < 4; u++) {
                float w = wv[u];
                const float* qd = sq + (d + u) * HV;
                const float* kd = sk + (d + u) * HV;
                aq[0] = fmaf(w, qd[0], aq[0]); aq[1] = fmaf(w, qd[1], aq[1]);
                aq[2] = fmaf(w, qd[2], aq[2]); aq[3] = fmaf(w, qd[3], aq[3]);
                ak[0] = fmaf(w, kd[0], ak[0]); ak[1] = fmaf(w, kd[1], ak[1]);
                ak[2] = fmaf(w, kd[2], ak[2]); ak[3] = fmaf(w, kd[3], ak[3]);
            }
        }
#pragma unroll
        for (int h = 0; h < HV; h++) {
            g_Wqkh[((long)l * 64 + r * 4 + h) * CV + cc] = __float2half(aq[h]);
            g_Wqkh[((long)l * 64 + 32 + r * 4 + h) * CV + cc] = __float2half(ak[h]);
        }
    }
}

// ================ FP16 mma.sync GEMM: 128x128 tile, BK=32, 8 warps 64x32 ================
// A [M,K] fp16 row-major, Bt [N,K] fp16 row-major. C: float (EPI 0,2) or half (EPI 1).
// EPI: 0 none (float out), 1 bias+relu -> HALF out, 2 bias+residual (float out)
template <int EPI>
__global__ __launch_bounds__(256)
void hgemm_k(const __half* __restrict__ A, const __half* __restrict__ Bt,
             void* __restrict__ Cv, int M, int Nc, int K,
             int lda, int ldbT, int ldc, long bz, long cz,
             const float* __restrict__ bias, const float* __restrict__ res) {
    Bt += (long)blockIdx.z * bz;
    float* Cf = (float*)Cv + (long)blockIdx.z * cz;
    __half* Ch = (__half*)Cv;
    __shared__ __align__(16) __half As[2][128][40];   // row stride 40 halves (80B)
    __shared__ __align__(16) __half Bs[2][128][40];

    const int tid = threadIdx.x;
    const int warp = tid >> 5, lane = tid & 31;
    const int wm = warp >> 2, wn = warp & 3;          // 2x4 warps, 64x32 each
    const int g = lane >> 2, c = lane & 3;
    const int m0 = blockIdx.y * 128, n0 = blockIdx.x * 128;

    uint32_t sA = (uint32_t)__cvta_generic_to_shared(&As[0][0][0]);
    uint32_t sB = (uint32_t)__cvta_generic_to_shared(&Bs[0][0][0]);

    float acc[4][4][4];
#pragma unroll
    for (int i = 0; i < 4; i++)
#pragma unroll
        for (int j = 0; j < 4; j++)
#pragma unroll
            for (int qq = 0; qq < 4; qq++) acc[i][j][qq] = 0.f;

    const int KT = K >> 5;

#define LOAD_STAGE(s, kt)                                                              \
    {                                                                                  \
        _Pragma("unroll")                                                              \
        for (int i = 0; i < 2; i++) {                                                  \
            int idx = tid + i * 256;                                                   \
            int r = idx >> 2, cc4 = idx & 3;                                           \
            bool p = (m0 + r) < M;                                                     \
            const __half* gp = A + (long)(m0 + r) * lda + (kt) * 32 + cc4 * 8;         \
            cp16(sA + ((s) * 128 + r) * 80 + cc4 * 16, gp, p);                         \
        }                                                                              \
        _Pragma("unroll")                                                              \
        for (int i = 0; i < 2; i++) {                                                  \
            int idx = tid + i * 256;                                                   \
            int r = idx >> 2, cc4 = idx & 3;                                           \
            bool p = (n0 + r) < Nc;                                                    \
            const __half* gp = Bt + (long)(n0 + r) * ldbT + (kt) * 32 + cc4 * 8;       \
            cp16(sB + ((s) * 128 + r) * 80 + cc4 * 16, gp, p);                         \
        }                                                                              \
        asm volatile("cp.async.commit_group;\n");                                      \
    }

    LOAD_STAGE(0, 0);

    for (int kt = 0; kt < KT; kt++) {
        asm volatile("cp.async.wait_group 0;\n");
        __syncthreads();
        if (kt + 1 < KT) LOAD_STAGE((kt + 1) & 1, kt + 1);
        int buf = kt & 1;
#pragma unroll
        for (int ks = 0; ks < 2; ks++) {
            int k0 = ks * 16;
            unsigned af[4][4], bf[4][2];
#pragma unroll
            for (int mt = 0; mt < 4; mt++) {
                int mr = wm * 64 + mt * 16;
                af[mt][0] = *(const unsigned*)&As[buf][mr + g][k0 + 2 * c];
                af[mt][1] = *(const unsigned*)&As[buf][mr + g + 8][k0 + 2 * c];
                af[mt][2] = *(const unsigned*)&As[buf][mr + g][k0 + 2 * c + 8];
                af[mt][3] = *(const unsigned*)&As[buf][mr + g + 8][k0 + 2 * c + 8];
            }
#pragma unroll
            for (int nt = 0; nt < 4; nt++) {
                int nc = wn * 32 + nt * 8;
                bf[nt][0] = *(const unsigned*)&Bs[buf][nc + g][k0 + 2 * c];
                bf[nt][1] = *(const unsigned*)&Bs[buf][nc + g][k0 + 2 * c + 8];
            }
#pragma unroll
            for (int mt = 0; mt < 4; mt++)
#pragma unroll
                for (int nt = 0; nt < 4; nt++)
                    mma_f16(acc[mt][nt], af[mt], bf[nt]);
        }
    }
#undef LOAD_STAGE

    // epilogue: acc[mt][nt][{0,1}] -> row g, cols 2c..2c+1; [{2,3}] -> row g+8
#pragma unroll
    for (int mt = 0; mt < 4; mt++) {
#pragma unroll
        for (int half = 0; half < 2; half++) {
            int m = m0 + wm * 64 + mt * 16 + g + half * 8;
            if (m >= M) continue;
#pragma unroll
            for (int nt = 0; nt < 4; nt++) {
                int n = n0 + wn * 32 + nt * 8 + 2 * c;
                if (n >= Nc) continue;
                float v0 = acc[mt][nt][half * 2 + 0];
                float v1 = acc[mt][nt][half * 2 + 1];
                if (EPI == 1) {
                    v0 = fmaxf(v0 + bias[n], 0.f);
                    v1 = fmaxf(v1 + bias[n + 1], 0.f);
                    *(__half2*)(Ch + (long)m * ldc + n) = __floats2half2_rn(v0, v1);
                } else if (EPI == 2) {
                    v0 = v0 + bias[n] + res[(long)m * Nc + n];
                    v1 = v1 + bias[n + 1] + res[(long)m * Nc + n + 1];
                    *(float2*)(Cf + (long)m * ldc + n) = make_float2(v0, v1);
                } else {
                    *(float2*)(Cf + (long)m * ldc + n) = make_float2(v0, v1);
                }
            }
        }
    }
}

// ---------------- P = We @ e, both layers ----------------
__global__ void p_kernel(const float* __restrict__ we, const float* __restrict__ ev) {
    int j = blockIdx.x * 8 + (threadIdx.x >> 5);
    int lane = threadIdx.x & 31;
    float a[8];
#pragma unroll
    for (int u = 0; u < 8; u++) a[u] = 0.f;
#pragma unroll
    for (int jj = 0; jj < 16; jj++) {
        int c = lane + 32 * jj;
        float w0 = we[(long)j * CV + c];
        float w1 = we[(long)EDV * CV + (long)j * CV + c];
        float4 e0 = *(const float4*)(ev + c * HV);
        float4 e1 = *(const float4*)(ev + CV * HV + c * HV);
        a[0] = fmaf(w0, e0.x, a[0]); a[1] = fmaf(w0, e0.y, a[1]);
        a[2] = fmaf(w0, e0.z, a[2]); a[3] = fmaf(w0, e0.w, a[3]);
        a[4] = fmaf(w1, e1.x, a[4]); a[5] = fmaf(w1, e1.y, a[5]);
        a[6] = fmaf(w1, e1.z, a[6]); a[7] = fmaf(w1, e1.w, a[7]);
    }
#pragma unroll
    for (int u = 0; u < 8; u++) a[u] = warp_red(a[u]);
    if (lane == 0) {
        *(float4*)(g_P + j * 8) = make_float4(a[0], a[1], a[2], a[3]);
        *(float4*)(g_P + j * 8 + 4) = make_float4(a[4], a[5], a[6], a[7]);
    }
}

// ---------------- ae = eattr @ P, both layers ----------------
__global__ void ae_kernel(const float* __restrict__ eattr) {
    int e = blockIdx.x * 8 + (threadIdx.x >> 5);
    int lane = threadIdx.x & 31;
    float a[8];
#pragma unroll
    for (int u = 0; u < 8; u++) a[u] = 0.f;
#pragma unroll
    for (int jj = 0; jj < 24; jj++) {
        int j = lane + 32 * jj;
        float v = eattr[(long)e * EDV + j];
        float4 p0 = *(const float4*)(g_P + j * 8);
        float4 p1 = *(const float4*)(g_P + j * 8 + 4);
        a[0] = fmaf(v, p0.x, a[0]); a[1] = fmaf(v, p0.y, a[1]);
        a[2] = fmaf(v, p0.z, a[2]); a[3] = fmaf(v, p0.w, a[3]);
        a[4] = fmaf(v, p1.x, a[4]); a[5] = fmaf(v, p1.y, a[5]);
        a[6] = fmaf(v, p1.z, a[6]); a[7] = fmaf(v, p1.w, a[7]);
    }
#pragma unroll
    for (int u = 0; u < 8; u++) a[u] = warp_red(a[u]);
    if (lane == 0) {
        *(float4*)(g_ae + (long)e * 8) = make_float4(a[0], a[1], a[2], a[3]);
        *(float4*)(g_ae + (long)e * 8 + 4) = make_float4(a[4], a[5], a[6], a[7]);
    }
}

// ---------------- per-layer reset of softmax state ----------------
__global__ void reset_nodes_kernel() {
    int i = blockIdx.x * blockDim.x + threadIdx.x;
    if (i < NV * HV) { g_maxu[i] = 0u; g_den[i] = 0.f; }
}

// ---------------- attention logits + leaky_relu + segment max ----------------
__global__ void logits_kernel(int l) {
    int e = blockIdx.x * blockDim.x + threadIdx.x;
    if (e >= EV) return;
    int dst = g_dst[e], src = g_src[e], t = g_typ[e];
    float4 ae = *(const float4*)(g_ae + (long)e * (LLV * HV) + l * HV);
    float4 qv = *(const float4*)(g_QK + (long)dst * 64 + t * 4);
    float4 kv = *(const float4*)(g_QK + (long)src * 64 + 32 + t * 4);
    float4 a;
    a.x = qv.x + kv.x + ae.x; a.x = a.x > 0.f ? a.x : 0.2f * a.x;
    a.y = qv.y + kv.y + ae.y; a.y = a.y > 0.f ? a.y : 0.2f * a.y;
    a.z = qv.z + kv.z + ae.z; a.z = a.z > 0.f ? a.z : 0.2f * a.z;
    a.w = qv.w + kv.w + ae.w; a.w = a.w > 0.f ? a.w : 0.2f * a.w;
    *(float4*)(g_alpha + (long)e * HV) = a;
    atomicMax(&g_maxu[dst * HV + 0], fenc(a.x));
    atomicMax(&g_maxu[dst * HV + 1], fenc(a.y));
    atomicMax(&g_maxu[dst * HV + 2], fenc(a.z));
    atomicMax(&g_maxu[dst * HV + 3], fenc(a.w));
}

// ---------------- exp + segment sum ----------------
__global__ void expsum_kernel() {
    int e = blockIdx.x * blockDim.x + threadIdx.x;
    if (e >= EV) return;
    int dst = g_dst[e];
    float4 a = *(const float4*)(g_alpha + (long)e * HV);
    a.x = expf(a.x - fdec(g_maxu[dst * HV + 0]));
    a.y = expf(a.y - fdec(g_maxu[dst * HV + 1]));
    a.z = expf(a.z - fdec(g_maxu[dst * HV + 2]));
    a.w = expf(a.w - fdec(g_maxu[dst * HV + 3]));
    *(float4*)(g_alpha + (long)e * HV) = a;
    atomicAdd(&g_den[dst * HV + 0], a.x);
    atomicAdd(&g_den[dst * HV + 1], a.y);
    atomicAdd(&g_den[dst * HV + 2], a.z);
    atomicAdd(&g_den[dst * HV + 3], a.w);
}

// ---------------- CSR aggregation (optionally emits fp16 copy) ----------------
__global__ void agg_kernel(const float* __restrict__ xin, float* __restrict__ xout,
                           __half* __restrict__ xout_h, const float* __restrict__ bias) {
    int n = blockIdx.x;
    int t = threadIdx.x;
    int h = t >> 5;
    float inv = 1.f / (g_den[n * HV + h] + 1e-16f);
    float4 acc = ((const float4*)bias)[t];
    float4 xr = ((const float4*)(xin + (long)n * CV))[t];
    acc.x += xr.x; acc.y += xr.y; acc.z += xr.z; acc.w += xr.w;
    int b0 = g_off[n], b1 = g_off[n + 1];
    for (int ii = b0; ii < b1; ii++) {
        int e = g_perm[ii];
        float coeff = g_alpha[e * HV + h] * inv;
        const float4* vp = (const float4*)(g_xw + ((long)g_src[e] * RV + g_typ[e]) * CV) + t;
        float4 vv = *vp;
        acc.x = fmaf(coeff, vv.x, acc.x);
        acc.y = fmaf(coeff, vv.y, acc.y);
        acc.z = fmaf(coeff, vv.z, acc.z);
        acc.w = fmaf(coeff, vv.w, acc.w);
    }
    ((float4*)(xout + (long)n * CV))[t] = acc;
    if (xout_h) {
        ((__half2*)(xout_h + (long)n * CV))[t * 2 + 0] = __floats2half2_rn(acc.x, acc.y);
        ((__half2*)(xout_h + (long)n * CV))[t * 2 + 1] = __floats2half2_rn(acc.z, acc.w);
    }
}

// ---------------- layernorm (optionally emits fp16 copy) ----------------
__global__ void ln_kernel(const float* __restrict__ in, const float* __restrict__ addpre,
                          const float* __restrict__ addpost, float* __restrict__ out,
                          __half* __restrict__ out_h,
                          const float* __restrict__ gamma, const float* __restrict__ beta) {
    int n = blockIdx.x, t = threadIdx.x;
    int lane = t & 31, w = t >> 5;
    __shared__ float sred[4];
    float4 x = ((const float4*)(in + (long)n * CV))[t];
    if (addpre) {
        float4 a = ((const float4*)(addpre + (long)n * CV))[t];
        x.x += a.x; x.y += a.y; x.z += a.z; x.w += a.w;
    }
    float s = x.x + x.y + x.z + x.w;
    s = warp_red(s);
    if (!lane) sred[w] = s;
    __syncthreads();
    float mean = (sred[0] + sred[1] + sred[2] + sred[3]) * (1.f / CV);
    __syncthreads();
    float dx = x.x - mean, dy = x.y - mean, dz = x.z - mean, dw = x.w - mean;
    float ss = dx * dx + dy * dy + dz * dz + dw * dw;
    ss = warp_red(ss);
    if (!lane) sred[w] = ss;
    __syncthreads();
    float var = (sred[0] + sred[1] + sred[2] + sred[3]) * (1.f / CV);
    float rstd = rsqrtf(var + 1e-5f);
    float4 g = ((const float4*)gamma)[t];
    float4 b = ((const float4*)beta)[t];
    float4 o;
    o.x = g.x * dx * rstd + b.x;
    o.y = g.y * dy * rstd + b.y;
    o.z = g.z * dz * rstd + b.z;
    o.w = g.w * dw * rstd + b.w;
    if (addpost) {
        float4 p = ((const float4*)(addpost + (long)n * CV))[t];
        o.x += p.x; o.y += p.y; o.z += p.z; o.w += p.w;
    }
    ((float4*)(out + (long)n * CV))[t] = o;
    if (out_h) {
        ((__half2*)(out_h + (long)n * CV))[t * 2 + 0] = __floats2half2_rn(o.x, o.y);
        ((__half2*)(out_h + (long)n * CV))[t * 2 + 1] = __floats2half2_rn(o.z, o.w);
    }
}

// ---------------- launcher ----------------
extern "C" void kernel_launch(void* const* d_in, const int* in_sizes, int n_in,
                              void* d_out, int out_size) {
    const float* x   = (const float*)d_in[0];
    const void*  ei  = d_in[1];
    const void*  et  = d_in[2];
    const float* eattr = (const float*)d_in[3];
    const float* W   = (const float*)d_in[4];
    const float* qm  = (const float*)d_in[5];
    const float* km  = (const float*)d_in[6];
    const float* em  = (const float*)d_in[7];
    const float* we  = (const float*)d_in[8];
    const float* cb  = (const float*)d_in[9];
    const float* lg  = (const float*)d_in[10];
    const float* lb  = (const float*)d_in[11];
    const float* f1w = (const float*)d_in[12];
    const float* f1b = (const float*)d_in[13];
    const float* f2w = (const float*)d_in[14];
    const float* f2b = (const float*)d_in[15];
    float* out = (float*)d_out;

    float *pxw, *pxA, *pxB, *ph0, *pQK;
    __half *pxh, *ph0h, *ph1h, *pWth, *pf1th, *pf2th, *pWqkh;
    cudaGetSymbolAddress((void**)&pxw, g_xw);
    cudaGetSymbolAddress((void**)&pxA, g_xA);
    cudaGetSymbolAddress((void**)&pxB, g_xB);
    cudaGetSymbolAddress((void**)&ph0, g_h0);
    cudaGetSymbolAddress((void**)&pQK, g_QK);
    cudaGetSymbolAddress((void**)&pxh, g_xh);
    cudaGetSymbolAddress((void**)&ph0h, g_h0h);
    cudaGetSymbolAddress((void**)&ph1h, g_h1h);
    cudaGetSymbolAddress((void**)&pWth, g_Wth);
    cudaGetSymbolAddress((void**)&pf1th, g_f1th);
    cudaGetSymbolAddress((void**)&pf2th, g_f2th);
    cudaGetSymbolAddress((void**)&pWqkh, g_Wqkh);

    const int TB = 256;
    const int EB = (EV + TB - 1) / TB;
    const int MT = (NV + 127) / 128;

    detect_kernel<<<1, 256>>>((const int*)ei, (const int*)et);
    convert_kernel<<<EB, TB>>>(ei, et);
    reset_cnt_kernel<<<(NV + TB - 1) / TB, TB>>>();
    hist_kernel<<<EB, TB>>>();
    scan_kernel<<<1, 1024>>>();
    scatter_kernel<<<EB, TB>>>();

    // edge-attr projections for BOTH layers in one eattr pass
    p_kernel<<<EDV / 8, 256>>>(we, em);
    ae_kernel<<<EV / 8, 256>>>(eattr);

    // fused QK weights + transposed fp16 weight copies
    wqk_kernel<<<LLV * RV, 256>>>(W, qm, km);
    {
        dim3 tb(32, 8);
        dim3 gw(CV / 32, CV / 32, LLV * RV);
        trans_cvt_kernel<<<gw, tb>>>(W, pWth, CV, CV);
        dim3 g1(2 * CV / 32, CV / 32, 1);
        trans_cvt_kernel<<<g1, tb>>>(f1w, pf1th, CV, 2 * CV);
        dim3 g2(CV / 32, 2 * CV / 32, 1);
        trans_cvt_kernel<<<g2, tb>>>(f2w, pf2th, 2 * CV, CV);
    }

    // fp16 copy of layer-0 activations
    cvt_half_kernel<<<(NV * CV / 4 + TB - 1) / TB, TB>>>(x, pxh, NV * CV / 4);

    for (int l = 0; l < LLV; l++) {
        const float* xin = (l == 0) ? x : pxB;
        float* xout = (l == 0) ? pxB : pxA;
        __half* xout_h = (l == 0) ? pxh : nullptr;

        // xw[n,r,:] = xh @ Wth[l,r]^T
        dim3 g1(CV / 128, MT, RV);
        hgemm_k<0><<<g1, 256>>>(pxh, pWth + (long)l * RV * CV * CV, pxw,
                                NV, CV, CV, CV, CV, RV * CV,
                                (long)CV * CV, (long)CV, nullptr, nullptr);

        // QK[n, 0..63] = xh @ Wqkh[l]^T
        dim3 gq(1, MT, 1);
        hgemm_k<0><<<gq, 256>>>(pxh, pWqkh + (long)l * 64 * CV, pQK,
                                NV, 64, CV, CV, CV, 64, 0, 0, nullptr, nullptr);

        reset_nodes_kernel<<<(NV * HV + TB - 1) / TB, TB>>>();
        logits_kernel<<<EB, TB>>>(l);
        expsum_kernel<<<EB, TB>>>();
        agg_kernel<<<NV, 128>>>(xin, xout, xout_h, cb + l * CV);
    }

    // h0 = LN(xA + enc_emb), also emit fp16 copy
    ln_kernel<<<NV, 128>>>(pxA, x, nullptr, ph0, ph0h, lg, lb);
    // h1h = half(relu(h0h @ f1th^T + b1))
    {
        dim3 g2(2 * CV / 128, MT, 1);
        hgemm_k<1><<<g2, 256>>>(ph0h, pf1th, ph1h, NV, 2 * CV, CV,
                                CV, CV, 2 * CV, 0, 0, f1b, nullptr);
    }
    // h2 = h1h @ f2th^T + b2 + h0  (into pxB)
    {
        dim3 g3(CV / 128, MT, 1);
        hgemm_k<2><<<g3, 256>>>(ph1h, pf2th, pxB, NV, CV, 2 * CV,
                                2 * CV, 2 * CV, CV, 0, 0, f2b, ph0);
    }
    // out = LN(h2) + enc_emb
    ln_kernel<<<NV, 128>>>(pxB, nullptr, x, out, nullptr, lg, lb);
}

// round 10
// speedup vs baseline: 1.4206x; 1.0526x over previous
#include <cuda_runtime.h>
#include <cuda_fp16.h>
#include <math.h>
#include <stdint.h>

#define NV 10000
#define EV 160000
#define CV 512
#define HV 4
#define RV 8
#define LLV 2
#define EDV 768
#define OV 128

// ---------------- scratch (device globals; no cudaMalloc allowed) ----------------
__device__ __half g_xwh[(size_t)NV * RV * CV]; // 82 MB, L2-resident gather source
__device__ float g_xA[NV * CV];
__device__ float g_xB[NV * CV];
__device__ float g_h0[NV * CV];
__device__ __half g_xh[NV * CV];
__device__ __half g_h0h[NV * CV];
__device__ __half g_h1h[NV * 2 * CV];
__device__ __half g_Wth[(size_t)LLV * RV * CV * CV]; // fp16 transposed weights [l][r][n][k]
__device__ __half g_f1th[2 * CV * CV];               // [n=1024][k=512]
__device__ __half g_f2th[CV * 2 * CV];               // [n=512][k=1024]
__device__ __half g_Wqkh[LLV * 64 * CV];             // [l][n=64][k=512]
__device__ float g_QK[NV * 64];
__device__ float g_P[EDV * LLV * HV];
__device__ float g_ae[(size_t)EV * LLV * HV];
__device__ float g_alpha[EV * HV];
__device__ unsigned g_maxu[NV * HV];
__device__ float g_den[NV * HV];
__device__ int g_src[EV], g_dst[EV], g_typ[EV];
__device__ int g_cnt[NV], g_off[NV + 1], g_cur[NV];
__device__ int g_perm[EV];
__device__ int g_flags[2];

// ---------------- helpers ----------------
__device__ __forceinline__ float warp_red(float v) {
#pragma unroll
    for (int s = 16; s; s >>= 1) v += __shfl_down_sync(0xffffffffu, v, s);
    return v;
}
__device__ __forceinline__ unsigned fenc(float f) {
    unsigned b = __float_as_uint(f);
    return (b & 0x80000000u) ? ~b : (b | 0x80000000u);
}
__device__ __forceinline__ float fdec(unsigned u) {
    return __uint_as_float((u & 0x80000000u) ? (u ^ 0x80000000u) : ~u);
}
__device__ __forceinline__ void mma_f16(float* d, const unsigned* a, const unsigned* b) {
    asm volatile(
        "mma.sync.aligned.m16n8k16.row.col.f32.f16.f16.f32 "
        "{%0,%1,%2,%3}, {%4,%5,%6,%7}, {%8,%9}, {%0,%1,%2,%3};"
        : "+f"(d[0]), "+f"(d[1]), "+f"(d[2]), "+f"(d[3])
        : "r"(a[0]), "r"(a[1]), "r"(a[2]), "r"(a[3]), "r"(b[0]), "r"(b[1]));
}
__device__ __forceinline__ void cp16(uint32_t dst, const void* src, bool p) {
    int sz = p ? 16 : 0;
    asm volatile("cp.async.cg.shared.global [%0], [%1], 16, %2;\n"
                 :: "r"(dst), "l"(src), "r"(sz));
}
__device__ __forceinline__ void ldsm4(unsigned& r0, unsigned& r1, unsigned& r2, unsigned& r3,
                                      uint32_t addr) {
    asm volatile("ldmatrix.sync.aligned.m8n8.x4.shared.b16 {%0,%1,%2,%3}, [%4];"
                 : "=r"(r0), "=r"(r1), "=r"(r2), "=r"(r3) : "r"(addr));
}

// ---------------- edge index dtype detection + conversion ----------------
__global__ void detect_kernel(const int* __restrict__ a, const int* __restrict__ b) {
    __shared__ int nz[2];
    if (threadIdx.x < 2) nz[threadIdx.x] = 0;
    __syncthreads();
    int i = threadIdx.x;
    if (a[2 * i + 1] != 0) atomicAdd(&nz[0], 1);
    if (b[2 * i + 1] != 0) atomicAdd(&nz[1], 1);
    __syncthreads();
    if (threadIdx.x == 0) { g_flags[0] = (nz[0] == 0); g_flags[1] = (nz[1] == 0); }
}

__global__ void convert_kernel(const void* __restrict__ ei, const void* __restrict__ et) {
    int e = blockIdx.x * blockDim.x + threadIdx.x;
    if (e >= EV) return;
    int f0 = g_flags[0], f1 = g_flags[1];
    int s, d, t;
    if (f0) {
        const long long* a = (const long long*)ei;
        s = (int)a[e]; d = (int)a[EV + e];
    } else {
        const int* a = (const int*)ei;
        s = a[e]; d = a[EV + e];
    }
    if (f1) t = (int)((const long long*)et)[e];
    else    t = ((const int*)et)[e];
    g_src[e] = s; g_dst[e] = d; g_typ[e] = t;
}

// ---------------- CSR build ----------------
__global__ void reset_cnt_kernel() {
    int i = blockIdx.x * blockDim.x + threadIdx.x;
    if (i < NV) g_cnt[i] = 0;
}
__global__ void hist_kernel() {
    int e = blockIdx.x * blockDim.x + threadIdx.x;
    if (e < EV) atomicAdd(&g_cnt[g_dst[e]], 1);
}
__global__ void scan_kernel() {
    __shared__ int sh[1024];
    __shared__ int carry;
    int t = threadIdx.x;
    if (t == 0) carry = 0;
    __syncthreads();
    for (int base = 0; base < NV; base += 1024) {
        int i = base + t;
        int v = (i < NV) ? g_cnt[i] : 0;
        sh[t] = v;
        __syncthreads();
        for (int s = 1; s < 1024; s <<= 1) {
            int add = (t >= s) ? sh[t - s] : 0;
            __syncthreads();
            sh[t] += add;
            __syncthreads();
        }
        int excl = sh[t] - v + carry;
        if (i < NV) { g_off[i] = excl; g_cur[i] = excl; }
        int tot = sh[1023];
        __syncthreads();
        if (t == 0) carry += tot;
        __syncthreads();
    }
    if (threadIdx.x == 0) g_off[NV] = carry;
}
__global__ void scatter_kernel() {
    int e = blockIdx.x * blockDim.x + threadIdx.x;
    if (e >= EV) return;
    int d = g_dst[e];
    int p = atomicAdd(&g_cur[d], 1);
    g_perm[p] = e;
}

// ---------------- elementwise fp16 conversion ----------------
__global__ void cvt_half_kernel(const float* __restrict__ in, __half* __restrict__ out, int n4) {
    int i = blockIdx.x * blockDim.x + threadIdx.x;
    if (i >= n4) return;
    float4 v = ((const float4*)in)[i];
    ((__half2*)out)[i * 2 + 0] = __floats2half2_rn(v.x, v.y);
    ((__half2*)out)[i * 2 + 1] = __floats2half2_rn(v.z, v.w);
}

// ---------------- transpose + fp16: in [K][N] -> out [N][K], z-batched ----------------
__global__ void trans_cvt_kernel(const float* __restrict__ in, __half* __restrict__ out,
                                 int K, int N) {
    in += (long)blockIdx.z * K * N;
    out += (long)blockIdx.z * K * N;
    __shared__ float tile[32][33];
    int k0 = blockIdx.y * 32, nb = blockIdx.x * 32;
    int tx = threadIdx.x, ty = threadIdx.y;  // 32x8
#pragma unroll
    for (int i = 0; i < 4; i++)
        tile[ty + i * 8][tx] = in[(long)(k0 + ty + i * 8) * N + nb + tx];
    __syncthreads();
#pragma unroll
    for (int i = 0; i < 4; i++)
        out[(long)(nb + ty + i * 8) * K + k0 + tx] = __float2half(tile[tx][ty + i * 8]);
}

// ---------------- Wqkh[l][n][k]: rows 0..31 = W[l,r]@q (n=r*4+h), 32..63 = W[l,r]@k ----------------
__global__ void wqk_kernel(const float* __restrict__ W, const float* __restrict__ q,
                           const float* __restrict__ k) {
    int l = blockIdx.x >> 3, r = blockIdx.x & 7;
    __shared__ float sq[CV * HV], sk[CV * HV];
    for (int i = threadIdx.x; i < CV * HV; i += 256) {
        sq[i] = q[(long)l * CV * HV + i];
        sk[i] = k[(long)l * CV * HV + i];
    }
    __syncthreads();
#pragma unroll
    for (int rep = 0; rep < 2; rep++) {
        int cc = threadIdx.x + rep * 256;
        const float* wrow = W + (((long)l * RV + r) * CV + cc) * CV;
        float aq[HV] = {0, 0, 0, 0}, ak[HV] = {0, 0, 0, 0};
        for (int d = 0; d < CV; d += 4) {
            float4 w4 = *(const float4*)(wrow + d);
            const float* wv = &w4.x;
#pragma unroll
            for (int u = 0; u < 4; u++) {
                float w = wv[u];
                const float* qd = sq + (d + u) * HV;
                const float* kd = sk + (d + u) * HV;
                aq[0] = fmaf(w, qd[0], aq[0]); aq[1] = fmaf(w, qd[1], aq[1]);
                aq[2] = fmaf(w, qd[2], aq[2]); aq[3] = fmaf(w, qd[3], aq[3]);
                ak[0] = fmaf(w, kd[0], ak[0]); ak[1] = fmaf(w, kd[1], ak[1]);
                ak[2] = fmaf(w, kd[2], ak[2]); ak[3] = fmaf(w, kd[3], ak[3]);
            }
        }
#pragma unroll
        for (int h = 0; h < HV; h++) {
            g_Wqkh[((long)l * 64 + r * 4 + h) * CV + cc] = __float2half(aq[h]);
            g_Wqkh[((long)l * 64 + 32 + r * 4 + h) * CV + cc] = __float2half(ak[h]);
        }
    }
}

// ========= FP16 mma.sync GEMM: 128x128 tile, BK=32, 8 warps 64x32, ldmatrix, 3-stage =========
// A [M,K] fp16 row-major, Bt [N,K] fp16 row-major.
// EPI: 0 float out, 1 bias+relu -> half out, 2 bias+residual float out, 3 half out
#define HG_STG 10240   // bytes per stage per operand (128 rows * 80B)
#define HG_SMEM (6 * HG_STG)

template <int EPI>
__global__ __launch_bounds__(256)
void hgemm_k(const __half* __restrict__ A, const __half* __restrict__ Bt,
             void* __restrict__ Cv, int M, int Nc, int K,
             int lda, int ldbT, int ldc, long bz, long cz,
             const float* __restrict__ bias, const float* __restrict__ res) {
    extern __shared__ __align__(16) char smraw[];
    uint32_t sAbase = (uint32_t)__cvta_generic_to_shared(smraw);
    uint32_t sBbase = sAbase + 3 * HG_STG;
    Bt += (long)blockIdx.z * bz;
    float* Cf = (float*)Cv + (long)blockIdx.z * cz;
    __half* Ch = (__half*)Cv + (long)blockIdx.z * cz;

    const int tid = threadIdx.x;
    const int warp = tid >> 5, lane = tid & 31;
    const int wm = warp >> 2, wn = warp & 3;          // 2x4 warps, 64x32 each
    const int g = lane >> 2, c = lane & 3;
    const int m0 = blockIdx.y * 128, n0 = blockIdx.x * 128;

    // ldmatrix lane address components
    const int alrow = (lane & 7) + ((lane >> 3) & 1) * 8;
    const int acolb = (lane >> 4) * 16;
    const int blrow = (lane & 7) + ((lane >> 4) & 1) * 8;
    const int bcolb = ((lane >> 3) & 1) * 16;
    const uint32_t aAddr0 = sAbase + (wm * 64 + alrow) * 80 + acolb;
    const uint32_t bAddr0 = sBbase + (wn * 32 + blrow) * 80 + bcolb;

    float acc[4][4][4];
#pragma unroll
    for (int i = 0; i < 4; i++)
#pragma unroll
        for (int j = 0; j < 4; j++)
#pragma unroll
            for (int qq = 0; qq < 4; qq++) acc[i][j][qq] = 0.f;

    const int KT = K >> 5;

#define LOAD_STAGE(s, kt)                                                              \
    {                                                                                  \
        _Pragma("unroll")                                                              \
        for (int i = 0; i < 2; i++) {                                                  \
            int idx = tid + i * 256;                                                   \
            int r = idx >> 2, cc4 = idx & 3;                                           \
            bool p = (m0 + r) < M;                                                     \
            const __half* gp = A + (long)(m0 + r) * lda + (kt) * 32 + cc4 * 8;         \
            cp16(sAbase + (s) * HG_STG + r * 80 + cc4 * 16, gp, p);                    \
        }                                                                              \
        _Pragma("unroll")                                                              \
        for (int i = 0; i < 2; i++) {                                                  \
            int idx = tid + i * 256;                                                   \
            int r = idx >> 2, cc4 = idx & 3;                                           \
            bool p = (n0 + r) < Nc;                                                    \
            const __half* gp = Bt + (long)(n0 + r) * ldbT + (kt) * 32 + cc4 * 8;       \
            cp16(sBbase + (s) * HG_STG + r * 80 + cc4 * 16, gp, p);                    \
        }                                                                              \
        asm volatile("cp.async.commit_group;\n");                                      \
    }

    LOAD_STAGE(0, 0);
    if (KT > 1) LOAD_STAGE(1, 1);

    int buf = 0;
    for (int kt = 0; kt < KT; kt++) {
        if (kt + 1 < KT) asm volatile("cp.async.wait_group 1;\n" ::: "memory");
        else             asm volatile("cp.async.wait_group 0;\n" ::: "memory");
        __syncthreads();
        if (kt + 2 < KT) {
            int s = (buf + 2) % 3;
            LOAD_STAGE(s, kt + 2);
        }
        uint32_t aB = aAddr0 + buf * HG_STG;
        uint32_t bB = bAddr0 + buf * HG_STG;
#pragma unroll
        for (int ks = 0; ks < 2; ks++) {
            unsigned af[4][4], bf[4][2];
#pragma unroll
            for (int mt = 0; mt < 4; mt++)
                ldsm4(af[mt][0], af[mt][1], af[mt][2], af[mt][3],
                      aB + mt * (16 * 80) + ks * 32);
#pragma unroll
            for (int pr = 0; pr < 2; pr++)
                ldsm4(bf[2 * pr][0], bf[2 * pr][1], bf[2 * pr + 1][0], bf[2 * pr + 1][1],
                      bB + pr * (16 * 80) + ks * 32);
#pragma unroll
            for (int mt = 0; mt < 4; mt++)
#pragma unroll
                for (int nt = 0; nt < 4; nt++)
                    mma_f16(acc[mt][nt], af[mt], bf[nt]);
        }
        buf = (buf + 1) % 3;
    }
#undef LOAD_STAGE

    // epilogue
#pragma unroll
    for (int mt = 0; mt < 4; mt++) {
#pragma unroll
        for (int half = 0; half < 2; half++) {
            int m = m0 + wm * 64 + mt * 16 + g + half * 8;
            if (m >= M) continue;
#pragma unroll
            for (int nt = 0; nt < 4; nt++) {
                int n = n0 + wn * 32 + nt * 8 + 2 * c;
                if (n >= Nc) continue;
                float v0 = acc[mt][nt][half * 2 + 0];
                float v1 = acc[mt][nt][half * 2 + 1];
                if (EPI == 1) {
                    v0 = fmaxf(v0 + bias[n], 0.f);
                    v1 = fmaxf(v1 + bias[n + 1], 0.f);
                    *(__half2*)(Ch + (long)m * ldc + n) = __floats2half2_rn(v0, v1);
                } else if (EPI == 2) {
                    v0 = v0 + bias[n] + res[(long)m * Nc + n];
                    v1 = v1 + bias[n + 1] + res[(long)m * Nc + n + 1];
                    *(float2*)(Cf + (long)m * ldc + n) = make_float2(v0, v1);
                } else if (EPI == 3) {
                    *(__half2*)(Ch + (long)m * ldc + n) = __floats2half2_rn(v0, v1);
                } else {
                    *(float2*)(Cf + (long)m * ldc + n) = make_float2(v0, v1);
                }
            }
        }
    }
}

// ---------------- P = We @ e, both layers ----------------
__global__ void p_kernel(const float* __restrict__ we, const float* __restrict__ ev) {
    int j = blockIdx.x * 8 + (threadIdx.x >> 5);
    int lane = threadIdx.x & 31;
    float a[8];
#pragma unroll
    for (int u = 0; u < 8; u++) a[u] = 0.f;
#pragma unroll
    for (int jj = 0; jj < 16; jj++) {
        int c = lane + 32 * jj;
        float w0 = we[(long)j * CV + c];
        float w1 = we[(long)EDV * CV + (long)j * CV + c];
        float4 e0 = *(const float4*)(ev + c * HV);
        float4 e1 = *(const float4*)(ev + CV * HV + c * HV);
        a[0] = fmaf(w0, e0.x, a[0]); a[1] = fmaf(w0, e0.y, a[1]);
        a[2] = fmaf(w0, e0.z, a[2]); a[3] = fmaf(w0, e0.w, a[3]);
        a[4] = fmaf(w1, e1.x, a[4]); a[5] = fmaf(w1, e1.y, a[5]);
        a[6] = fmaf(w1, e1.z, a[6]); a[7] = fmaf(w1, e1.w, a[7]);
    }
#pragma unroll
    for (int u = 0; u < 8; u++) a[u] = warp_red(a[u]);
    if (lane == 0) {
        *(float4*)(g_P + j * 8) = make_float4(a[0], a[1], a[2], a[3]);
        *(float4*)(g_P + j * 8 + 4) = make_float4(a[4], a[5], a[6], a[7]);
    }
}

// ---------------- ae = eattr @ P, both layers ----------------
__global__ void ae_kernel(const float* __restrict__ eattr) {
    int e = blockIdx.x * 8 + (threadIdx.x >> 5);
    int lane = threadIdx.x & 31;
    float a[8];
#pragma unroll
    for (int u = 0; u < 8; u++) a[u] = 0.f;
#pragma unroll
    for (int jj = 0; jj < 24; jj++) {
        int j = lane + 32 * jj;
        float v = eattr[(long)e * EDV + j];
        float4 p0 = *(const float4*)(g_P + j * 8);
        float4 p1 = *(const float4*)(g_P + j * 8 + 4);
        a[0] = fmaf(v, p0.x, a[0]); a[1] = fmaf(v, p0.y, a[1]);
        a[2] = fmaf(v, p0.z, a[2]); a[3] = fmaf(v, p0.w, a[3]);
        a[4] = fmaf(v, p1.x, a[4]); a[5] = fmaf(v, p1.y, a[5]);
        a[6] = fmaf(v, p1.z, a[6]); a[7] = fmaf(v, p1.w, a[7]);
    }
#pragma unroll
    for (int u = 0; u < 8; u++) a[u] = warp_red(a[u]);
    if (lane == 0) {
        *(float4*)(g_ae + (long)e * 8) = make_float4(a[0], a[1], a[2], a[3]);
        *(float4*)(g_ae + (long)e * 8 + 4) = make_float4(a[4], a[5], a[6], a[7]);
    }
}

// ---------------- per-layer reset of softmax state ----------------
__global__ void reset_nodes_kernel() {
    int i = blockIdx.x * blockDim.x + threadIdx.x;
    if (i < NV * HV) { g_maxu[i] = 0u; g_den[i] = 0.f; }
}

// ---------------- attention logits + leaky_relu + segment max ----------------
__global__ void logits_kernel(int l) {
    int e = blockIdx.x * blockDim.x + threadIdx.x;
    if (e >= EV) return;
    int dst = g_dst[e], src = g_src[e], t = g_typ[e];
    float4 ae = *(const float4*)(g_ae + (long)e * (LLV * HV) + l * HV);
    float4 qv = *(const float4*)(g_QK + (long)dst * 64 + t * 4);
    float4 kv = *(const float4*)(g_QK + (long)src * 64 + 32 + t * 4);
    float4 a;
    a.x = qv.x + kv.x + ae.x; a.x = a.x > 0.f ? a.x : 0.2f * a.x;
    a.y = qv.y + kv.y + ae.y; a.y = a.y > 0.f ? a.y : 0.2f * a.y;
    a.z = qv.z + kv.z + ae.z; a.z = a.z > 0.f ? a.z : 0.2f * a.z;
    a.w = qv.w + kv.w + ae.w; a.w = a.w > 0.f ? a.w : 0.2f * a.w;
    *(float4*)(g_alpha + (long)e * HV) = a;
    atomicMax(&g_maxu[dst * HV + 0], fenc(a.x));
    atomicMax(&g_maxu[dst * HV + 1], fenc(a.y));
    atomicMax(&g_maxu[dst * HV + 2], fenc(a.z));
    atomicMax(&g_maxu[dst * HV + 3], fenc(a.w));
}

// ---------------- exp + segment sum ----------------
__global__ void expsum_kernel() {
    int e = blockIdx.x * blockDim.x + threadIdx.x;
    if (e >= EV) return;
    int dst = g_dst[e];
    float4 a = *(const float4*)(g_alpha + (long)e * HV);
    a.x = expf(a.x - fdec(g_maxu[dst * HV + 0]));
    a.y = expf(a.y - fdec(g_maxu[dst * HV + 1]));
    a.z = expf(a.z - fdec(g_maxu[dst * HV + 2]));
    a.w = expf(a.w - fdec(g_maxu[dst * HV + 3]));
    *(float4*)(g_alpha + (long)e * HV) = a;
    atomicAdd(&g_den[dst * HV + 0], a.x);
    atomicAdd(&g_den[dst * HV + 1], a.y);
    atomicAdd(&g_den[dst * HV + 2], a.z);
    atomicAdd(&g_den[dst * HV + 3], a.w);
}

// ---------------- CSR aggregation over fp16 xw (optionally emits fp16 copy) ----------------
__global__ void agg_kernel(const float* __restrict__ xin, float* __restrict__ xout,
                           __half* __restrict__ xout_h, const float* __restrict__ bias) {
    int n = blockIdx.x;
    int t = threadIdx.x;
    int h = t >> 5;
    float inv = 1.f / (g_den[n * HV + h] + 1e-16f);
    float4 acc = ((const float4*)bias)[t];
    float4 xr = ((const float4*)(xin + (long)n * CV))[t];
    acc.x += xr.x; acc.y += xr.y; acc.z += xr.z; acc.w += xr.w;
    int b0 = g_off[n], b1 = g_off[n + 1];
    for (int ii = b0; ii < b1; ii++) {
        int e = g_perm[ii];
        float coeff = g_alpha[e * HV + h] * inv;
        const __half* row = g_xwh + ((long)g_src[e] * RV + g_typ[e]) * CV;
        uint2 u = *(const uint2*)(row + t * 4);
        float2 f01 = __half22float2(*(__half2*)&u.x);
        float2 f23 = __half22float2(*(__half2*)&u.y);
        acc.x = fmaf(coeff, f01.x, acc.x);
        acc.y = fmaf(coeff, f01.y, acc.y);
        acc.z = fmaf(coeff, f23.x, acc.z);
        acc.w = fmaf(coeff, f23.y, acc.w);
    }
    ((float4*)(xout + (long)n * CV))[t] = acc;
    if (xout_h) {
        ((__half2*)(xout_h + (long)n * CV))[t * 2 + 0] = __floats2half2_rn(acc.x, acc.y);
        ((__half2*)(xout_h + (long)n * CV))[t * 2 + 1] = __floats2half2_rn(acc.z, acc.w);
    }
}

// ---------------- layernorm (optionally emits fp16 copy) ----------------
__global__ void ln_kernel(const float* __restrict__ in, const float* __restrict__ addpre,
                          const float* __restrict__ addpost, float* __restrict__ out,
                          __half* __restrict__ out_h,
                          const float* __restrict__ gamma, const float* __restrict__ beta) {
    int n = blockIdx.x, t = threadIdx.x;
    int lane = t & 31, w = t >> 5;
    __shared__ float sred[4];
    float4 x = ((const float4*)(in + (long)n * CV))[t];
    if (addpre) {
        float4 a = ((const float4*)(addpre + (long)n * CV))[t];
        x.x += a.x; x.y += a.y; x.z += a.z; x.w += a.w;
    }
    float s = x.x + x.y + x.z + x.w;
    s = warp_red(s);
    if (!lane) sred[w] = s;
    __syncthreads();
    float mean = (sred[0] + sred[1] + sred[2] + sred[3]) * (1.f / CV);
    __syncthreads();
    float dx = x.x - mean, dy = x.y - mean, dz = x.z - mean, dw = x.w - mean;
    float ss = dx * dx + dy * dy + dz * dz + dw * dw;
    ss = warp_red(ss);
    if (!lane) sred[w] = ss;
    __syncthreads();
    float var = (sred[0] + sred[1] + sred[2] + sred[3]) * (1.f / CV);
    float rstd = rsqrtf(var + 1e-5f);
    float4 g = ((const float4*)gamma)[t];
    float4 b = ((const float4*)beta)[t];
    float4 o;
    o.x = g.x * dx * rstd + b.x;
    o.y = g.y * dy * rstd + b.y;
    o.z = g.z * dz * rstd + b.z;
    o.w = g.w * dw * rstd + b.w;
    if (addpost) {
        float4 p = ((const float4*)(addpost + (long)n * CV))[t];
        o.x += p.x; o.y += p.y; o.z += p.z; o.w += p.w;
    }
    ((float4*)(out + (long)n * CV))[t] = o;
    if (out_h) {
        ((__half2*)(out_h + (long)n * CV))[t * 2 + 0] = __floats2half2_rn(o.x, o.y);
        ((__half2*)(out_h + (long)n * CV))[t * 2 + 1] = __floats2half2_rn(o.z, o.w);
    }
}

// ---------------- launcher ----------------
extern "C" void kernel_launch(void* const* d_in, const int* in_sizes, int n_in,
                              void* d_out, int out_size) {
    const float* x   = (const float*)d_in[0];
    const void*  ei  = d_in[1];
    const void*  et  = d_in[2];
    const float* eattr = (const float*)d_in[3];
    const float* W   = (const float*)d_in[4];
    const float* qm  = (const float*)d_in[5];
    const float* km  = (const float*)d_in[6];
    const float* em  = (const float*)d_in[7];
    const float* we  = (const float*)d_in[8];
    const float* cb  = (const float*)d_in[9];
    const float* lg  = (const float*)d_in[10];
    const float* lb  = (const float*)d_in[11];
    const float* f1w = (const float*)d_in[12];
    const float* f1b = (const float*)d_in[13];
    const float* f2w = (const float*)d_in[14];
    const float* f2b = (const float*)d_in[15];
    float* out = (float*)d_out;

    float *pxA, *pxB, *ph0, *pQK;
    __half *pxwh, *pxh, *ph0h, *ph1h, *pWth, *pf1th, *pf2th, *pWqkh;
    cudaGetSymbolAddress((void**)&pxwh, g_xwh);
    cudaGetSymbolAddress((void**)&pxA, g_xA);
    cudaGetSymbolAddress((void**)&pxB, g_xB);
    cudaGetSymbolAddress((void**)&ph0, g_h0);
    cudaGetSymbolAddress((void**)&pQK, g_QK);
    cudaGetSymbolAddress((void**)&pxh, g_xh);
    cudaGetSymbolAddress((void**)&ph0h, g_h0h);
    cudaGetSymbolAddress((void**)&ph1h, g_h1h);
    cudaGetSymbolAddress((void**)&pWth, g_Wth);
    cudaGetSymbolAddress((void**)&pf1th, g_f1th);
    cudaGetSymbolAddress((void**)&pf2th, g_f2th);
    cudaGetSymbolAddress((void**)&pWqkh, g_Wqkh);

    cudaFuncSetAttribute(hgemm_k<0>, cudaFuncAttributeMaxDynamicSharedMemorySize, HG_SMEM);
    cudaFuncSetAttribute(hgemm_k<1>, cudaFuncAttributeMaxDynamicSharedMemorySize, HG_SMEM);
    cudaFuncSetAttribute(hgemm_k<2>, cudaFuncAttributeMaxDynamicSharedMemorySize, HG_SMEM);
    cudaFuncSetAttribute(hgemm_k<3>, cudaFuncAttributeMaxDynamicSharedMemorySize, HG_SMEM);

    const int TB = 256;
    const int EB = (EV + TB - 1) / TB;
    const int MT = (NV + 127) / 128;

    detect_kernel<<<1, 256>>>((const int*)ei, (const int*)et);
    convert_kernel<<<EB, TB>>>(ei, et);
    reset_cnt_kernel<<<(NV + TB - 1) / TB, TB>>>();
    hist_kernel<<<EB, TB>>>();
    scan_kernel<<<1, 1024>>>();
    scatter_kernel<<<EB, TB>>>();

    // edge-attr projections for BOTH layers in one eattr pass
    p_kernel<<<EDV / 8, 256>>>(we, em);
    ae_kernel<<<EV / 8, 256>>>(eattr);

    // fused QK weights + transposed fp16 weight copies
    wqk_kernel<<<LLV * RV, 256>>>(W, qm, km);
    {
        dim3 tb(32, 8);
        dim3 gw(CV / 32, CV / 32, LLV * RV);
        trans_cvt_kernel<<<gw, tb>>>(W, pWth, CV, CV);
        dim3 g1(2 * CV / 32, CV / 32, 1);
        trans_cvt_kernel<<<g1, tb>>>(f1w, pf1th, CV, 2 * CV);
        dim3 g2(CV / 32, 2 * CV / 32, 1);
        trans_cvt_kernel<<<g2, tb>>>(f2w, pf2th, 2 * CV, CV);
    }

    // fp16 copy of layer-0 activations
    cvt_half_kernel<<<(NV * CV / 4 + TB - 1) / TB, TB>>>(x, pxh, NV * CV / 4);

    for (int l = 0; l < LLV; l++) {
        const float* xin = (l == 0) ? x : pxB;
        float* xout = (l == 0) ? pxB : pxA;
        __half* xout_h = (l == 0) ? pxh : nullptr;

        // xwh[n,r,:] = xh @ Wth[l,r]^T  (fp16 out, L2-resident gather source)
        dim3 g1(CV / 128, MT, RV);
        hgemm_k<3><<<g1, 256, HG_SMEM>>>(pxh, pWth + (long)l * RV * CV * CV, pxwh,
                                         NV, CV, CV, CV, CV, RV * CV,
                                         (long)CV * CV, (long)CV, nullptr, nullptr);

        // QK[n, 0..63] = xh @ Wqkh[l]^T
        dim3 gq(1, MT, 1);
        hgemm_k<0><<<gq, 256, HG_SMEM>>>(pxh, pWqkh + (long)l * 64 * CV, pQK,
                                         NV, 64, CV, CV, CV, 64, 0, 0, nullptr, nullptr);

        reset_nodes_kernel<<<(NV * HV + TB - 1) / TB, TB>>>();
        logits_kernel<<<EB, TB>>>(l);
        expsum_kernel<<<EB, TB>>>();
        agg_kernel<<<NV, 128>>>(xin, xout, xout_h, cb + l * CV);
    }

    // h0 = LN(xA + enc_emb), also emit fp16 copy
    ln_kernel<<<NV, 128>>>(pxA, x, nullptr, ph0, ph0h, lg, lb);
    // h1h = half(relu(h0h @ f1th^T + b1))
    {
        dim3 g2(2 * CV / 128, MT, 1);
        hgemm_k<1><<<g2, 256, HG_SMEM>>>(ph0h, pf1th, ph1h, NV, 2 * CV, CV,
                                         CV, CV, 2 * CV, 0, 0, f1b, nullptr);
    }
    // h2 = h1h @ f2th^T + b2 + h0  (into pxB)
    {
        dim3 g3(CV / 128, MT, 1);
        hgemm_k<2><<<g3, 256, HG_SMEM>>>(ph1h, pf2th, pxB, NV, CV, 2 * CV,
                                         2 * CV, 2 * CV, CV, 0, 0, f2b, ph0);
    }
    // out = LN(h2) + enc_emb
    ln_kernel<<<NV, 128>>>(pxB, nullptr, x, out, nullptr, lg, lb);
}

// round 15
// speedup vs baseline: 1.5522x; 1.0927x over previous
#include <cuda_runtime.h>
#include <cuda_fp16.h>
#include <math.h>
#include <stdint.h>

#define NV 10000
#define EV 160000
#define CV 512
#define HV 4
#define RV 8
#define LLV 2
#define EDV 768
#define OV 128

// ---------------- scratch (device globals; no cudaMalloc allowed) ----------------
__device__ __half g_xwh[(size_t)NV * RV * CV]; // 82 MB, L2-resident gather source
__device__ float g_xA[NV * CV];
__device__ float g_xB[NV * CV];
__device__ float g_h0[NV * CV];
__device__ __half g_xh[NV * CV];
__device__ __half g_h0h[NV * CV];
__device__ __half g_h1h[NV * 2 * CV];
__device__ __half g_Wth[(size_t)LLV * RV * CV * CV]; // fp16 transposed weights [l][r][n][k]
__device__ __half g_f1th[2 * CV * CV];               // [n=1024][k=512]
__device__ __half g_f2th[CV * 2 * CV];               // [n=512][k=1024]
__device__ __half g_Wqkh[LLV * 64 * CV];             // [l][n=64][k=512]
__device__ float g_QK[NV * 64];
__device__ float g_P[EDV * LLV * HV];
__device__ float g_ae[(size_t)EV * LLV * HV];
__device__ float g_alpha[EV * HV];
__device__ float g_den[NV * HV];
__device__ int g_src[EV], g_dst[EV], g_typ[EV];
__device__ int g_cnt[NV], g_off[NV + 1], g_cur[NV];
__device__ int g_perm[EV];
__device__ int g_flags[2];

// ---------------- helpers ----------------
__device__ __forceinline__ float warp_red(float v) {
#pragma unroll
    for (int s = 16; s; s >>= 1) v += __shfl_down_sync(0xffffffffu, v, s);
    return v;
}
__device__ __forceinline__ void mma_f16(float* d, const unsigned* a, const unsigned* b) {
    asm volatile(
        "mma.sync.aligned.m16n8k16.row.col.f32.f16.f16.f32 "
        "{%0,%1,%2,%3}, {%4,%5,%6,%7}, {%8,%9}, {%0,%1,%2,%3};"
        : "+f"(d[0]), "+f"(d[1]), "+f"(d[2]), "+f"(d[3])
        : "r"(a[0]), "r"(a[1]), "r"(a[2]), "r"(a[3]), "r"(b[0]), "r"(b[1]));
}
__device__ __forceinline__ void cp16(uint32_t dst, const void* src, bool p) {
    int sz = p ? 16 : 0;
    asm volatile("cp.async.cg.shared.global [%0], [%1], 16, %2;\n"
                 :: "r"(dst), "l"(src), "r"(sz));
}
__device__ __forceinline__ void ldsm4(unsigned& r0, unsigned& r1, unsigned& r2, unsigned& r3,
                                      uint32_t addr) {
    asm volatile("ldmatrix.sync.aligned.m8n8.x4.shared.b16 {%0,%1,%2,%3}, [%4];"
                 : "=r"(r0), "=r"(r1), "=r"(r2), "=r"(r3) : "r"(addr));
}

// ---------------- edge index dtype detection + conversion ----------------
__global__ void detect_kernel(const int* __restrict__ a, const int* __restrict__ b) {
    __shared__ int nz[2];
    if (threadIdx.x < 2) nz[threadIdx.x] = 0;
    __syncthreads();
    int i = threadIdx.x;
    if (a[2 * i + 1] != 0) atomicAdd(&nz[0], 1);
    if (b[2 * i + 1] != 0) atomicAdd(&nz[1], 1);
    __syncthreads();
    if (threadIdx.x == 0) { g_flags[0] = (nz[0] == 0); g_flags[1] = (nz[1] == 0); }
}

__global__ void convert_kernel(const void* __restrict__ ei, const void* __restrict__ et) {
    int e = blockIdx.x * blockDim.x + threadIdx.x;
    if (e >= EV) return;
    int f0 = g_flags[0], f1 = g_flags[1];
    int s, d, t;
    if (f0) {
        const long long* a = (const long long*)ei;
        s = (int)a[e]; d = (int)a[EV + e];
    } else {
        const int* a = (const int*)ei;
        s = a[e]; d = a[EV + e];
    }
    if (f1) t = (int)((const long long*)et)[e];
    else    t = ((const int*)et)[e];
    g_src[e] = s; g_dst[e] = d; g_typ[e] = t;
}

// ---------------- CSR build ----------------
__global__ void reset_cnt_kernel() {
    int i = blockIdx.x * blockDim.x + threadIdx.x;
    if (i < NV) g_cnt[i] = 0;
}
__global__ void hist_kernel() {
    int e = blockIdx.x * blockDim.x + threadIdx.x;
    if (e < EV) atomicAdd(&g_cnt[g_dst[e]], 1);
}
__global__ void scan_kernel() {
    __shared__ int sh[1024];
    __shared__ int carry;
    int t = threadIdx.x;
    if (t == 0) carry = 0;
    __syncthreads();
    for (int base = 0; base < NV; base += 1024) {
        int i = base + t;
        int v = (i < NV) ? g_cnt[i] : 0;
        sh[t] = v;
        __syncthreads();
        for (int s = 1; s < 1024; s <<= 1) {
            int add = (t >= s) ? sh[t - s] : 0;
            __syncthreads();
            sh[t] += add;
            __syncthreads();
        }
        int excl = sh[t] - v + carry;
        if (i < NV) { g_off[i] = excl; g_cur[i] = excl; }
        int tot = sh[1023];
        __syncthreads();
        if (t == 0) carry += tot;
        __syncthreads();
    }
    if (threadIdx.x == 0) g_off[NV] = carry;
}
__global__ void scatter_kernel() {
    int e = blockIdx.x * blockDim.x + threadIdx.x;
    if (e >= EV) return;
    int d = g_dst[e];
    int p = atomicAdd(&g_cur[d], 1);
    g_perm[p] = e;
}

// ---------------- elementwise fp16 conversion ----------------
__global__ void cvt_half_kernel(const float* __restrict__ in, __half* __restrict__ out, int n4) {
    int i = blockIdx.x * blockDim.x + threadIdx.x;
    if (i >= n4) return;
    float4 v = ((const float4*)in)[i];
    ((__half2*)out)[i * 2 + 0] = __floats2half2_rn(v.x, v.y);
    ((__half2*)out)[i * 2 + 1] = __floats2half2_rn(v.z, v.w);
}

// ---------------- transpose + fp16: in [K][N] -> out [N][K], z-batched ----------------
__global__ void trans_cvt_kernel(const float* __restrict__ in, __half* __restrict__ out,
                                 int K, int N) {
    in += (long)blockIdx.z * K * N;
    out += (long)blockIdx.z * K * N;
    __shared__ float tile[32][33];
    int k0 = blockIdx.y * 32, nb = blockIdx.x * 32;
    int tx = threadIdx.x, ty = threadIdx.y;  // 32x8
#pragma unroll
    for (int i = 0; i < 4; i++)
        tile[ty + i * 8][tx] = in[(long)(k0 + ty + i * 8) * N + nb + tx];
    __syncthreads();
#pragma unroll
    for (int i = 0; i < 4; i++)
        out[(long)(nb + ty + i * 8) * K + k0 + tx] = __float2half(tile[tx][ty + i * 8]);
}

// ---------------- Wqkh[l][n][k]: rows 0..31 = W[l,r]@q (n=r*4+h), 32..63 = W[l,r]@k ----------------
__global__ void wqk_kernel(const float* __restrict__ W, const float* __restrict__ q,
                           const float* __restrict__ k) {
    int l = blockIdx.x >> 3, r = blockIdx.x & 7;
    __shared__ float sq[CV * HV], sk[CV * HV];
    for (int i = threadIdx.x; i < CV * HV; i += 256) {
        sq[i] = q[(long)l * CV * HV + i];
        sk[i] = k[(long)l * CV * HV + i];
    }
    __syncthreads();
#pragma unroll
    for (int rep = 0; rep < 2; rep++) {
        int cc = threadIdx.x + rep * 256;
        const float* wrow = W + (((long)l * RV + r) * CV + cc) * CV;
        float aq[HV] = {0, 0, 0, 0}, ak[HV] = {0, 0, 0, 0};
        for (int d = 0; d < CV; d += 4) {
            float4 w4 = *(const float4*)(wrow + d);
            const float* wv = &w4.x;
#pragma unroll
            for (int u = 0; u < 4; u++) {
                float w = wv[u];
                const float* qd = sq + (d + u) * HV;
                const float* kd = sk + (d + u) * HV;
                aq[0] = fmaf(w, qd[0], aq[0]); aq[1] = fmaf(w, qd[1], aq[1]);
                aq[2] = fmaf(w, qd[2], aq[2]); aq[3] = fmaf(w, qd[3], aq[3]);
                ak[0] = fmaf(w, kd[0], ak[0]); ak[1] = fmaf(w, kd[1], ak[1]);
                ak[2] = fmaf(w, kd[2], ak[2]); ak[3] = fmaf(w, kd[3], ak[3]);
            }
        }
#pragma unroll
        for (int h = 0; h < HV; h++) {
            g_Wqkh[((long)l * 64 + r * 4 + h) * CV + cc] = __float2half(aq[h]);
            g_Wqkh[((long)l * 64 + 32 + r * 4 + h) * CV + cc] = __float2half(ak[h]);
        }
    }
}

// ==== FP16 mma.sync GEMM: 128x128 tile, BK=32, 4 warps (2x2) of 64x64, ldmatrix, 3-stage ====
// A [M,K] fp16 row-major, Bt [N,K] fp16 row-major.
// EPI: 0 float out, 1 bias+relu -> half out, 2 bias+residual float out, 3 half out
#define HG_STG 10240   // bytes per stage per operand (128 rows * 80B)
#define HG_SMEM (6 * HG_STG)

template <int EPI>
__global__ __launch_bounds__(128)
void hgemm_k(const __half* __restrict__ A, const __half* __restrict__ Bt,
             void* __restrict__ Cv, int M, int Nc, int K,
             int lda, int ldbT, int ldc, long bz, long cz,
             const float* __restrict__ bias, const float* __restrict__ res) {
    extern __shared__ __align__(16) char smraw[];
    uint32_t sAbase = (uint32_t)__cvta_generic_to_shared(smraw);
    uint32_t sBbase = sAbase + 3 * HG_STG;
    Bt += (long)blockIdx.z * bz;
    float* Cf = (float*)Cv + (long)blockIdx.z * cz;
    __half* Ch = (__half*)Cv + (long)blockIdx.z * cz;

    const int tid = threadIdx.x;
    const int warp = tid >> 5, lane = tid & 31;
    const int wm = warp >> 1, wn = warp & 1;          // 2x2 warps, 64x64 each
    const int g = lane >> 2, c = lane & 3;
    const int m0 = blockIdx.y * 128, n0 = blockIdx.x * 128;

    // ldmatrix lane address components
    const int alrow = (lane & 7) + ((lane >> 3) & 1) * 8;
    const int acolb = (lane >> 4) * 16;
    const int blrow = (lane & 7) + ((lane >> 4) & 1) * 8;
    const int bcolb = ((lane >> 3) & 1) * 16;
    const uint32_t aAddr0 = sAbase + (wm * 64 + alrow) * 80 + acolb;
    const uint32_t bAddr0 = sBbase + (wn * 64 + blrow) * 80 + bcolb;

    float acc[4][8][4];
#pragma unroll
    for (int i = 0; i < 4; i++)
#pragma unroll
        for (int j = 0; j < 8; j++)
#pragma unroll
            for (int qq = 0; qq < 4; qq++) acc[i][j][qq] = 0.f;

    const int KT = K >> 5;

#define LOAD_STAGE(s, kt)                                                              \
    {                                                                                  \
        _Pragma("unroll")                                                              \
        for (int i = 0; i < 4; i++) {                                                  \
            int idx = tid + i * 128;                                                   \
            int r = idx >> 2, cc4 = idx & 3;                                           \
            bool p = (m0 + r) < M;                                                     \
            const __half* gp = A + (long)(m0 + r) * lda + (kt) * 32 + cc4 * 8;         \
            cp16(sAbase + (s) * HG_STG + r * 80 + cc4 * 16, gp, p);                    \
        }                                                                              \
        _Pragma("unroll")                                                              \
        for (int i = 0; i < 4; i++) {                                                  \
            int idx = tid + i * 128;                                                   \
            int r = idx >> 2, cc4 = idx & 3;                                           \
            bool p = (n0 + r) < Nc;                                                    \
            const __half* gp = Bt + (long)(n0 + r) * ldbT + (kt) * 32 + cc4 * 8;       \
            cp16(sBbase + (s) * HG_STG + r * 80 + cc4 * 16, gp, p);                    \
        }                                                                              \
        asm volatile("cp.async.commit_group;\n");                                      \
    }

    LOAD_STAGE(0, 0);
    if (KT > 1) LOAD_STAGE(1, 1);

    int buf = 0;
    for (int kt = 0; kt < KT; kt++) {
        if (kt + 1 < KT) asm volatile("cp.async.wait_group 1;\n" ::: "memory");
        else             asm volatile("cp.async.wait_group 0;\n" ::: "memory");
        __syncthreads();
        if (kt + 2 < KT) {
            int s = (buf + 2) % 3;
            LOAD_STAGE(s, kt + 2);
        }
        uint32_t aB = aAddr0 + buf * HG_STG;
        uint32_t bB = bAddr0 + buf * HG_STG;
#pragma unroll
        for (int ks = 0; ks < 2; ks++) {
            unsigned af[4][4], bf[8][2];
#pragma unroll
            for (int mt = 0; mt < 4; mt++)
                ldsm4(af[mt][0], af[mt][1], af[mt][2], af[mt][3],
                      aB + mt * (16 * 80) + ks * 32);
#pragma unroll
            for (int pr = 0; pr < 4; pr++)
                ldsm4(bf[2 * pr][0], bf[2 * pr][1], bf[2 * pr + 1][0], bf[2 * pr + 1][1],
                      bB + pr * (16 * 80) + ks * 32);
#pragma unroll
            for (int mt = 0; mt < 4; mt++)
#pragma unroll
                for (int nt = 0; nt < 8; nt++)
                    mma_f16(acc[mt][nt], af[mt], bf[nt]);
        }
        buf = (buf + 1) % 3;
    }
#undef LOAD_STAGE

    // epilogue
#pragma unroll
    for (int mt = 0; mt < 4; mt++) {
#pragma unroll
        for (int half = 0; half < 2; half++) {
            int m = m0 + wm * 64 + mt * 16 + g + half * 8;
            if (m >= M) continue;
#pragma unroll
            for (int nt = 0; nt < 8; nt++) {
                int n = n0 + wn * 64 + nt * 8 + 2 * c;
                if (n >= Nc) continue;
                float v0 = acc[mt][nt][half * 2 + 0];
                float v1 = acc[mt][nt][half * 2 + 1];
                if (EPI == 1) {
                    v0 = fmaxf(v0 + bias[n], 0.f);
                    v1 = fmaxf(v1 + bias[n + 1], 0.f);
                    *(__half2*)(Ch + (long)m * ldc + n) = __floats2half2_rn(v0, v1);
                } else if (EPI == 2) {
                    v0 = v0 + bias[n] + res[(long)m * Nc + n];
                    v1 = v1 + bias[n + 1] + res[(long)m * Nc + n + 1];
                    *(float2*)(Cf + (long)m * ldc + n) = make_float2(v0, v1);
                } else if (EPI == 3) {
                    *(__half2*)(Ch + (long)m * ldc + n) = __floats2half2_rn(v0, v1);
                } else {
                    *(float2*)(Cf + (long)m * ldc + n) = make_float2(v0, v1);
                }
            }
        }
    }
}

// ---------------- P = We @ e, both layers ----------------
__global__ void p_kernel(const float* __restrict__ we, const float* __restrict__ ev) {
    int j = blockIdx.x * 8 + (threadIdx.x >> 5);
    int lane = threadIdx.x & 31;
    float a[8];
#pragma unroll
    for (int u = 0; u < 8; u++) a[u] = 0.f;
#pragma unroll
    for (int jj = 0; jj < 16; jj++) {
        int c = lane + 32 * jj;
        float w0 = we[(long)j * CV + c];
        float w1 = we[(long)EDV * CV + (long)j * CV + c];
        float4 e0 = *(const float4*)(ev + c * HV);
        float4 e1 = *(const float4*)(ev + CV * HV + c * HV);
        a[0] = fmaf(w0, e0.x, a[0]); a[1] = fmaf(w0, e0.y, a[1]);
        a[2] = fmaf(w0, e0.z, a[2]); a[3] = fmaf(w0, e0.w, a[3]);
        a[4] = fmaf(w1, e1.x, a[4]); a[5] = fmaf(w1, e1.y, a[5]);
        a[6] = fmaf(w1, e1.z, a[6]); a[7] = fmaf(w1, e1.w, a[7]);
    }
#pragma unroll
    for (int u = 0; u < 8; u++) a[u] = warp_red(a[u]);
    if (lane == 0) {
        *(float4*)(g_P + j * 8) = make_float4(a[0], a[1], a[2], a[3]);
        *(float4*)(g_P + j * 8 + 4) = make_float4(a[4], a[5], a[6], a[7]);
    }
}

// ---------------- ae = eattr @ P, both layers ----------------
__global__ void ae_kernel(const float* __restrict__ eattr) {
    int e = blockIdx.x * 8 + (threadIdx.x >> 5);
    int lane = threadIdx.x & 31;
    float a[8];
#pragma unroll
    for (int u = 0; u < 8; u++) a[u] = 0.f;
#pragma unroll
    for (int jj = 0; jj < 24; jj++) {
        int j = lane + 32 * jj;
        float v = eattr[(long)e * EDV + j];
        float4 p0 = *(const float4*)(g_P + j * 8);
        float4 p1 = *(const float4*)(g_P + j * 8 + 4);
        a[0] = fmaf(v, p0.x, a[0]); a[1] = fmaf(v, p0.y, a[1]);
        a[2] = fmaf(v, p0.z, a[2]); a[3] = fmaf(v, p0.w, a[3]);
        a[4] = fmaf(v, p1.x, a[4]); a[5] = fmaf(v, p1.y, a[5]);
        a[6] = fmaf(v, p1.z, a[6]); a[7] = fmaf(v, p1.w, a[7]);
    }
#pragma unroll
    for (int u = 0; u < 8; u++) a[u] = warp_red(a[u]);
    if (lane == 0) {
        *(float4*)(g_ae + (long)e * 8) = make_float4(a[0], a[1], a[2], a[3]);
        *(float4*)(g_ae + (long)e * 8 + 4) = make_float4(a[4], a[5], a[6], a[7]);
    }
}

// ---------------- per-layer reset of softmax denominators ----------------
__global__ void reset_nodes_kernel() {
    int i = blockIdx.x * blockDim.x + threadIdx.x;
    if (i < NV * HV) g_den[i] = 0.f;
}

// ----- attention logits + leaky_relu + exp + segment sum (no max subtraction; exact) -----
__global__ void logexp_kernel(int l) {
    int e = blockIdx.x * blockDim.x + threadIdx.x;
    if (e >= EV) return;
    int dst = g_dst[e], src = g_src[e], t = g_typ[e];
    float4 ae = *(const float4*)(g_ae + (long)e * (LLV * HV) + l * HV);
    float4 qv = *(const float4*)(g_QK + (long)dst * 64 + t * 4);
    float4 kv = *(const float4*)(g_QK + (long)src * 64 + 32 + t * 4);
    float4 a;
    a.x = qv.x + kv.x + ae.x; a.x = a.x > 0.f ? a.x : 0.2f * a.x;
    a.y = qv.y + kv.y + ae.y; a.y = a.y > 0.f ? a.y : 0.2f * a.y;
    a.z = qv.z + kv.z + ae.z; a.z = a.z > 0.f ? a.z : 0.2f * a.z;
    a.w = qv.w + kv.w + ae.w; a.w = a.w > 0.f ? a.w : 0.2f * a.w;
    a.x = expf(a.x); a.y = expf(a.y); a.z = expf(a.z); a.w = expf(a.w);
    *(float4*)(g_alpha + (long)e * HV) = a;
    atomicAdd(&g_den[dst * HV + 0], a.x);
    atomicAdd(&g_den[dst * HV + 1], a.y);
    atomicAdd(&g_den[dst * HV + 2], a.z);
    atomicAdd(&g_den[dst * HV + 3], a.w);
}

// ---------------- CSR aggregation over fp16 xw (optionally emits fp16 copy) ----------------
__global__ void agg_kernel(const float* __restrict__ xin, float* __restrict__ xout,
                           __half* __restrict__ xout_h, const float* __restrict__ bias) {
    int n = blockIdx.x;
    int t = threadIdx.x;
    int h = t >> 5;
    float inv = 1.f / (g_den[n * HV + h] + 1e-16f);
    float4 acc = ((const float4*)bias)[t];
    float4 xr = ((const float4*)(xin + (long)n * CV))[t];
    acc.x += xr.x; acc.y += xr.y; acc.z += xr.z; acc.w += xr.w;
    int b0 = g_off[n], b1 = g_off[n + 1];
    for (int ii = b0; ii < b1; ii++) {
        int e = g_perm[ii];
        float coeff = g_alpha[e * HV + h] * inv;
        const __half* row = g_xwh + ((long)g_src[e] * RV + g_typ[e]) * CV;
        uint2 u = *(const uint2*)(row + t * 4);
        float2 f01 = __half22float2(*(__half2*)&u.x);
        float2 f23 = __half22float2(*(__half2*)&u.y);
        acc.x = fmaf(coeff, f01.x, acc.x);
        acc.y = fmaf(coeff, f01.y, acc.y);
        acc.z = fmaf(coeff, f23.x, acc.z);
        acc.w = fmaf(coeff, f23.y, acc.w);
    }
    ((float4*)(xout + (long)n * CV))[t] = acc;
    if (xout_h) {
        ((__half2*)(xout_h + (long)n * CV))[t * 2 + 0] = __floats2half2_rn(acc.x, acc.y);
        ((__half2*)(xout_h + (long)n * CV))[t * 2 + 1] = __floats2half2_rn(acc.z, acc.w);
    }
}

// ---------------- layernorm (optionally emits fp16 copy) ----------------
__global__ void ln_kernel(const float* __restrict__ in, const float* __restrict__ addpre,
                          const float* __restrict__ addpost, float* __restrict__ out,
                          __half* __restrict__ out_h,
                          const float* __restrict__ gamma, const float* __restrict__ beta) {
    int n = blockIdx.x, t = threadIdx.x;
    int lane = t & 31, w = t >> 5;
    __shared__ float sred[4];
    float4 x = ((const float4*)(in + (long)n * CV))[t];
    if (addpre) {
        float4 a = ((const float4*)(addpre + (long)n * CV))[t];
        x.x += a.x; x.y += a.y; x.z += a.z; x.w += a.w;
    }
    float s = x.x + x.y + x.z + x.w;
    s = warp_red(s);
    if (!lane) sred[w] = s;
    __syncthreads();
    float mean = (sred[0] + sred[1] + sred[2] + sred[3]) * (1.f / CV);
    __syncthreads();
    float dx = x.x - mean, dy = x.y - mean, dz = x.z - mean, dw = x.w - mean;
    float ss = dx * dx + dy * dy + dz * dz + dw * dw;
    ss = warp_red(ss);
    if (!lane) sred[w] = ss;
    __syncthreads();
    float var = (sred[0] + sred[1] + sred[2] + sred[3]) * (1.f / CV);
    float rstd = rsqrtf(var + 1e-5f);
    float4 g = ((const float4*)gamma)[t];
    float4 b = ((const float4*)beta)[t];
    float4 o;
    o.x = g.x * dx * rstd + b.x;
    o.y = g.y * dy * rstd + b.y;
    o.z = g.z * dz * rstd + b.z;
    o.w = g.w * dw * rstd + b.w;
    if (addpost) {
        float4 p = ((const float4*)(addpost + (long)n * CV))[t];
        o.x += p.x; o.y += p.y; o.z += p.z; o.w += p.w;
    }
    ((float4*)(out + (long)n * CV))[t] = o;
    if (out_h) {
        ((__half2*)(out_h + (long)n * CV))[t * 2 + 0] = __floats2half2_rn(o.x, o.y);
        ((__half2*)(out_h + (long)n * CV))[t * 2 + 1] = __floats2half2_rn(o.z, o.w);
    }
}

// ---------------- launcher ----------------
extern "C" void kernel_launch(void* const* d_in, const int* in_sizes, int n_in,
                              void* d_out, int out_size) {
    const float* x   = (const float*)d_in[0];
    const void*  ei  = d_in[1];
    const void*  et  = d_in[2];
    const float* eattr = (const float*)d_in[3];
    const float* W   = (const float*)d_in[4];
    const float* qm  = (const float*)d_in[5];
    const float* km  = (const float*)d_in[6];
    const float* em  = (const float*)d_in[7];
    const float* we  = (const float*)d_in[8];
    const float* cb  = (const float*)d_in[9];
    const float* lg  = (const float*)d_in[10];
    const float* lb  = (const float*)d_in[11];
    const float* f1w = (const float*)d_in[12];
    const float* f1b = (const float*)d_in[13];
    const float* f2w = (const float*)d_in[14];
    const float* f2b = (const float*)d_in[15];
    float* out = (float*)d_out;

    float *pxA, *pxB, *ph0, *pQK;
    __half *pxwh, *pxh, *ph0h, *ph1h, *pWth, *pf1th, *pf2th, *pWqkh;
    cudaGetSymbolAddress((void**)&pxwh, g_xwh);
    cudaGetSymbolAddress((void**)&pxA, g_xA);
    cudaGetSymbolAddress((void**)&pxB, g_xB);
    cudaGetSymbolAddress((void**)&ph0, g_h0);
    cudaGetSymbolAddress((void**)&pQK, g_QK);
    cudaGetSymbolAddress((void**)&pxh, g_xh);
    cudaGetSymbolAddress((void**)&ph0h, g_h0h);
    cudaGetSymbolAddress((void**)&ph1h, g_h1h);
    cudaGetSymbolAddress((void**)&pWth, g_Wth);
    cudaGetSymbolAddress((void**)&pf1th, g_f1th);
    cudaGetSymbolAddress((void**)&pf2th, g_f2th);
    cudaGetSymbolAddress((void**)&pWqkh, g_Wqkh);

    cudaFuncSetAttribute(hgemm_k<0>, cudaFuncAttributeMaxDynamicSharedMemorySize, HG_SMEM);
    cudaFuncSetAttribute(hgemm_k<1>, cudaFuncAttributeMaxDynamicSharedMemorySize, HG_SMEM);
    cudaFuncSetAttribute(hgemm_k<2>, cudaFuncAttributeMaxDynamicSharedMemorySize, HG_SMEM);
    cudaFuncSetAttribute(hgemm_k<3>, cudaFuncAttributeMaxDynamicSharedMemorySize, HG_SMEM);

    const int TB = 256;
    const int EB = (EV + TB - 1) / TB;
    const int MT = (NV + 127) / 128;

    detect_kernel<<<1, 256>>>((const int*)ei, (const int*)et);
    convert_kernel<<<EB, TB>>>(ei, et);
    reset_cnt_kernel<<<(NV + TB - 1) / TB, TB>>>();
    hist_kernel<<<EB, TB>>>();
    scan_kernel<<<1, 1024>>>();
    scatter_kernel<<<EB, TB>>>();

    // edge-attr projections for BOTH layers in one eattr pass
    p_kernel<<<EDV / 8, 256>>>(we, em);
    ae_kernel<<<EV / 8, 256>>>(eattr);

    // fused QK weights + transposed fp16 weight copies
    wqk_kernel<<<LLV * RV, 256>>>(W, qm, km);
    {
        dim3 tb(32, 8);
        dim3 gw(CV / 32, CV / 32, LLV * RV);
        trans_cvt_kernel<<<gw, tb>>>(W, pWth, CV, CV);
        dim3 g1(2 * CV / 32, CV / 32, 1);
        trans_cvt_kernel<<<g1, tb>>>(f1w, pf1th, CV, 2 * CV);
        dim3 g2(CV / 32, 2 * CV / 32, 1);
        trans_cvt_kernel<<<g2, tb>>>(f2w, pf2th, 2 * CV, CV);
    }

    // fp16 copy of layer-0 activations
    cvt_half_kernel<<<(NV * CV / 4 + TB - 1) / TB, TB>>>(x, pxh, NV * CV / 4);

    for (int l = 0; l < LLV; l++) {
        const float* xin = (l == 0) ? x : pxB;
        float* xout = (l == 0) ? pxB : pxA;
        __half* xout_h = (l == 0) ? pxh : nullptr;

        // xwh[n,r,:] = xh @ Wth[l,r]^T  (fp16 out, L2-resident gather source)
        dim3 g1(CV / 128, MT, RV);
        hgemm_k<3><<<g1, 128, HG_SMEM>>>(pxh, pWth + (long)l * RV * CV * CV, pxwh,
                                         NV, CV, CV, CV, CV, RV * CV,
                                         (long)CV * CV, (long)CV, nullptr, nullptr);

        // QK[n, 0..63] = xh @ Wqkh[l]^T
        dim3 gq(1, MT, 1);
        hgemm_k<0><<<gq, 128, HG_SMEM>>>(pxh, pWqkh + (long)l * 64 * CV, pQK,
                                         NV, 64, CV, CV, CV, 64, 0, 0, nullptr, nullptr);

        reset_nodes_kernel<<<(NV * HV + TB - 1) / TB, TB>>>();
        logexp_kernel<<<EB, TB>>>(l);
        agg_kernel<<<NV, 128>>>(xin, xout, xout_h, cb + l * CV);
    }

    // h0 = LN(xA + enc_emb), also emit fp16 copy
    ln_kernel<<<NV, 128>>>(pxA, x, nullptr, ph0, ph0h, lg, lb);
    // h1h = half(relu(h0h @ f1th^T + b1))
    {
        dim3 g2(2 * CV / 128, MT, 1);
        hgemm_k<1><<<g2, 128, HG_SMEM>>>(ph0h, pf1th, ph1h, NV, 2 * CV, CV,
                                         CV, CV, 2 * CV, 0, 0, f1b, nullptr);
    }
    // h2 = h1h @ f2th^T + b2 + h0  (into pxB)
    {
        dim3 g3(CV / 128, MT, 1);
        hgemm_k<2><<<g3, 128, HG_SMEM>>>(ph1h, pf2th, pxB, NV, CV, 2 * CV,
                                         2 * CV, 2 * CV, CV, 0, 0, f2b, ph0);
    }
    // out = LN(h2) + enc_emb
    ln_kernel<<<NV, 128>>>(pxB, nullptr, x, out, nullptr, lg, lb);
}

// round 17
// speedup vs baseline: 1.6063x; 1.0348x over previous
#include <cuda_runtime.h>
#include <cuda_fp16.h>
#include <math.h>
#include <stdint.h>

#define NV 10000
#define EV 160000
#define CV 512
#define HV 4
#define RV 8
#define LLV 2
#define EDV 768
#define OV 128
#define MAXD 1024

// ---------------- scratch (device globals; no cudaMalloc allowed) ----------------
__device__ __half g_xwh[(size_t)NV * RV * CV]; // 82 MB, L2-resident gather source
__device__ float g_xA[NV * CV];
__device__ float g_xB[NV * CV];
__device__ float g_h0[NV * CV];
__device__ __half g_xh[NV * CV];
__device__ __half g_h0h[NV * CV];
__device__ __half g_h1h[NV * 2 * CV];
__device__ __half g_Wth[(size_t)LLV * RV * CV * CV]; // fp16 transposed weights [l][r][n][k]
__device__ __half g_f1th[2 * CV * CV];               // [n=1024][k=512]
__device__ __half g_f2th[CV * 2 * CV];               // [n=512][k=1024]
__device__ __half g_Wqkh[LLV * 64 * CV];             // [l][n=64][k=512]
__device__ float g_QK[NV * 64];
__device__ float g_P[EDV * LLV * HV];
__device__ float g_ae[(size_t)EV * LLV * HV];        // CSR-ordered: [pos][l*4+h]
__device__ int g_src[EV], g_dst[EV], g_typ[EV];
__device__ int g_cnt[NV], g_off[NV + 1], g_cur[NV];
__device__ int g_gidx[EV];                           // CSR-ordered src*8+typ
__device__ int g_epos[EV];                           // edge -> CSR position
__device__ int g_flags[2];

// ---------------- helpers ----------------
__device__ __forceinline__ float warp_red(float v) {
#pragma unroll
    for (int s = 16; s; s >>= 1) v += __shfl_down_sync(0xffffffffu, v, s);
    return v;
}
__device__ __forceinline__ void mma_f16(float* d, const unsigned* a, const unsigned* b) {
    asm volatile(
        "mma.sync.aligned.m16n8k16.row.col.f32.f16.f16.f32 "
        "{%0,%1,%2,%3}, {%4,%5,%6,%7}, {%8,%9}, {%0,%1,%2,%3};"
        : "+f"(d[0]), "+f"(d[1]), "+f"(d[2]), "+f"(d[3])
        : "r"(a[0]), "r"(a[1]), "r"(a[2]), "r"(a[3]), "r"(b[0]), "r"(b[1]));
}
__device__ __forceinline__ void cp16(uint32_t dst, const void* src, bool p) {
    int sz = p ? 16 : 0;
    asm volatile("cp.async.cg.shared.global [%0], [%1], 16, %2;\n"
                 :: "r"(dst), "l"(src), "r"(sz));
}
__device__ __forceinline__ void ldsm4(unsigned& r0, unsigned& r1, unsigned& r2, unsigned& r3,
                                      uint32_t addr) {
    asm volatile("ldmatrix.sync.aligned.m8n8.x4.shared.b16 {%0,%1,%2,%3}, [%4];"
                 : "=r"(r0), "=r"(r1), "=r"(r2), "=r"(r3) : "r"(addr));
}

// ---------------- edge index dtype detection + conversion ----------------
__global__ void detect_kernel(const int* __restrict__ a, const int* __restrict__ b) {
    __shared__ int nz[2];
    if (threadIdx.x < 2) nz[threadIdx.x] = 0;
    __syncthreads();
    int i = threadIdx.x;
    if (a[2 * i + 1] != 0) atomicAdd(&nz[0], 1);
    if (b[2 * i + 1] != 0) atomicAdd(&nz[1], 1);
    __syncthreads();
    if (threadIdx.x == 0) { g_flags[0] = (nz[0] == 0); g_flags[1] = (nz[1] == 0); }
}

__global__ void convert_kernel(const void* __restrict__ ei, const void* __restrict__ et) {
    int e = blockIdx.x * blockDim.x + threadIdx.x;
    if (e >= EV) return;
    int f0 = g_flags[0], f1 = g_flags[1];
    int s, d, t;
    if (f0) {
        const long long* a = (const long long*)ei;
        s = (int)a[e]; d = (int)a[EV + e];
    } else {
        const int* a = (const int*)ei;
        s = a[e]; d = a[EV + e];
    }
    if (f1) t = (int)((const long long*)et)[e];
    else    t = ((const int*)et)[e];
    g_src[e] = s; g_dst[e] = d; g_typ[e] = t;
}

// ---------------- CSR build ----------------
__global__ void reset_cnt_kernel() {
    int i = blockIdx.x * blockDim.x + threadIdx.x;
    if (i < NV) g_cnt[i] = 0;
}
__global__ void hist_kernel() {
    int e = blockIdx.x * blockDim.x + threadIdx.x;
    if (e < EV) atomicAdd(&g_cnt[g_dst[e]], 1);
}
__global__ void scan_kernel() {
    __shared__ int sh[1024];
    __shared__ int carry;
    int t = threadIdx.x;
    if (t == 0) carry = 0;
    __syncthreads();
    for (int base = 0; base < NV; base += 1024) {
        int i = base + t;
        int v = (i < NV) ? g_cnt[i] : 0;
        sh[t] = v;
        __syncthreads();
        for (int s = 1; s < 1024; s <<= 1) {
            int add = (t >= s) ? sh[t - s] : 0;
            __syncthreads();
            sh[t] += add;
            __syncthreads();
        }
        int excl = sh[t] - v + carry;
        if (i < NV) { g_off[i] = excl; g_cur[i] = excl; }
        int tot = sh[1023];
        __syncthreads();
        if (t == 0) carry += tot;
        __syncthreads();
    }
    if (threadIdx.x == 0) g_off[NV] = carry;
}
__global__ void scatter_kernel() {
    int e = blockIdx.x * blockDim.x + threadIdx.x;
    if (e >= EV) return;
    int d = g_dst[e];
    int p = atomicAdd(&g_cur[d], 1);
    g_gidx[p] = g_src[e] * RV + g_typ[e];
    g_epos[e] = p;
}

// ---------------- elementwise fp16 conversion ----------------
__global__ void cvt_half_kernel(const float* __restrict__ in, __half* __restrict__ out, int n4) {
    int i = blockIdx.x * blockDim.x + threadIdx.x;
    if (i >= n4) return;
    float4 v = ((const float4*)in)[i];
    ((__half2*)out)[i * 2 + 0] = __floats2half2_rn(v.x, v.y);
    ((__half2*)out)[i * 2 + 1] = __floats2half2_rn(v.z, v.w);
}

// ---------------- transpose + fp16: in [K][N] -> out [N][K], z-batched ----------------
__global__ void trans_cvt_kernel(const float* __restrict__ in, __half* __restrict__ out,
                                 int K, int N) {
    in += (long)blockIdx.z * K * N;
    out += (long)blockIdx.z * K * N;
    __shared__ float tile[32][33];
    int k0 = blockIdx.y * 32, nb = blockIdx.x * 32;
    int tx = threadIdx.x, ty = threadIdx.y;  // 32x8
#pragma unroll
    for (int i = 0; i < 4; i++)
        tile[ty + i * 8][tx] = in[(long)(k0 + ty + i * 8) * N + nb + tx];
    __syncthreads();
#pragma unroll
    for (int i = 0; i < 4; i++)
        out[(long)(nb + ty + i * 8) * K + k0 + tx] = __float2half(tile[tx][ty + i * 8]);
}

// ---------------- Wqkh[l][n][k]: rows 0..31 = W[l,r]@q (n=r*4+h), 32..63 = W[l,r]@k ----------------
__global__ void wqk_kernel(const float* __restrict__ W, const float* __restrict__ q,
                           const float* __restrict__ k) {
    int l = blockIdx.x >> 3, r = blockIdx.x & 7;
    __shared__ float sq[CV * HV], sk[CV * HV];
    for (int i = threadIdx.x; i < CV * HV; i += 256) {
        sq[i] = q[(long)l * CV * HV + i];
        sk[i] = k[(long)l * CV * HV + i];
    }
    __syncthreads();
#pragma unroll
    for (int rep = 0; rep < 2; rep++) {
        int cc = threadIdx.x + rep * 256;
        const float* wrow = W + (((long)l * RV + r) * CV + cc) * CV;
        float aq[HV] = {0, 0, 0, 0}, ak[HV] = {0, 0, 0, 0};
        for (int d = 0; d < CV; d += 4) {
            float4 w4 = *(const float4*)(wrow + d);
            const float* wv = &w4.x;
#pragma unroll
            for (int u = 0; u < 4; u++) {
                float w = wv[u];
                const float* qd = sq + (d + u) * HV;
                const float* kd = sk + (d + u) * HV;
                aq[0] = fmaf(w, qd[0], aq[0]); aq[1] = fmaf(w, qd[1], aq[1]);
                aq[2] = fmaf(w, qd[2], aq[2]); aq[3] = fmaf(w, qd[3], aq[3]);
                ak[0] = fmaf(w, kd[0], ak[0]); ak[1] = fmaf(w, kd[1], ak[1]);
                ak[2] = fmaf(w, kd[2], ak[2]); ak[3] = fmaf(w, kd[3], ak[3]);
            }
        }
#pragma unroll
        for (int h = 0; h < HV; h++) {
            g_Wqkh[((long)l * 64 + r * 4 + h) * CV + cc] = __float2half(aq[h]);
            g_Wqkh[((long)l * 64 + 32 + r * 4 + h) * CV + cc] = __float2half(ak[h]);
        }
    }
}

// ==== FP16 mma.sync GEMM: 128x128 tile, BK=32, 4 warps (2x2) of 64x64, ldmatrix, 3-stage ====
#define HG_STG 10240
#define HG_SMEM (6 * HG_STG)

template <int EPI>
__global__ __launch_bounds__(128)
void hgemm_k(const __half* __restrict__ A, const __half* __restrict__ Bt,
             void* __restrict__ Cv, int M, int Nc, int K,
             int lda, int ldbT, int ldc, long bz, long cz,
             const float* __restrict__ bias, const float* __restrict__ res) {
    extern __shared__ __align__(16) char smraw[];
    uint32_t sAbase = (uint32_t)__cvta_generic_to_shared(smraw);
    uint32_t sBbase = sAbase + 3 * HG_STG;
    Bt += (long)blockIdx.z * bz;
    float* Cf = (float*)Cv + (long)blockIdx.z * cz;
    __half* Ch = (__half*)Cv + (long)blockIdx.z * cz;

    const int tid = threadIdx.x;
    const int warp = tid >> 5, lane = tid & 31;
    const int wm = warp >> 1, wn = warp & 1;
    const int g = lane >> 2, c = lane & 3;
    const int m0 = blockIdx.y * 128, n0 = blockIdx.x * 128;

    const int alrow = (lane & 7) + ((lane >> 3) & 1) * 8;
    const int acolb = (lane >> 4) * 16;
    const int blrow = (lane & 7) + ((lane >> 4) & 1) * 8;
    const int bcolb = ((lane >> 3) & 1) * 16;
    const uint32_t aAddr0 = sAbase + (wm * 64 + alrow) * 80 + acolb;
    const uint32_t bAddr0 = sBbase + (wn * 64 + blrow) * 80 + bcolb;

    float acc[4][8][4];
#pragma unroll
    for (int i = 0; i < 4; i++)
#pragma unroll
        for (int j = 0; j < 8; j++)
#pragma unroll
            for (int qq = 0; qq < 4; qq++) acc[i][j][qq] = 0.f;

    const int KT = K >> 5;

#define LOAD_STAGE(s, kt)                                                              \
    {                                                                                  \
        _Pragma("unroll")                                                              \
        for (int i = 0; i < 4; i++) {                                                  \
            int idx = tid + i * 128;                                                   \
            int r = idx >> 2, cc4 = idx & 3;                                           \
            bool p = (m0 + r) < M;                                                     \
            const __half* gp = A + (long)(m0 + r) * lda + (kt) * 32 + cc4 * 8;         \
            cp16(sAbase + (s) * HG_STG + r * 80 + cc4 * 16, gp, p);                    \
        }                                                                              \
        _Pragma("unroll")                                                              \
        for (int i = 0; i < 4; i++) {                                                  \
            int idx = tid + i * 128;                                                   \
            int r = idx >> 2, cc4 = idx & 3;                                           \
            bool p = (n0 + r) < Nc;                                                    \
            const __half* gp = Bt + (long)(n0 + r) * ldbT + (kt) * 32 + cc4 * 8;       \
            cp16(sBbase + (s) * HG_STG + r * 80 + cc4 * 16, gp, p);                    \
        }                                                                              \
        asm volatile("cp.async.commit_group;\n");                                      \
    }

    LOAD_STAGE(0, 0);
    if (KT > 1) LOAD_STAGE(1, 1);

    int buf = 0;
    for (int kt = 0; kt < KT; kt++) {
        if (kt + 1 < KT) asm volatile("cp.async.wait_group 1;\n" ::: "memory");
        else             asm volatile("cp.async.wait_group 0;\n" ::: "memory");
        __syncthreads();
        if (kt + 2 < KT) {
            int s = (buf + 2) % 3;
            LOAD_STAGE(s, kt + 2);
        }
        uint32_t aB = aAddr0 + buf * HG_STG;
        uint32_t bB = bAddr0 + buf * HG_STG;
#pragma unroll
        for (int ks = 0; ks < 2; ks++) {
            unsigned af[4][4], bf[8][2];
#pragma unroll
            for (int mt = 0; mt < 4; mt++)
                ldsm4(af[mt][0], af[mt][1], af[mt][2], af[mt][3],
                      aB + mt * (16 * 80) + ks * 32);
#pragma unroll
            for (int pr = 0; pr < 4; pr++)
                ldsm4(bf[2 * pr][0], bf[2 * pr][1], bf[2 * pr + 1][0], bf[2 * pr + 1][1],
                      bB + pr * (16 * 80) + ks * 32);
#pragma unroll
            for (int mt = 0; mt < 4; mt++)
#pragma unroll
                for (int nt = 0; nt < 8; nt++)
                    mma_f16(acc[mt][nt], af[mt], bf[nt]);
        }
        buf = (buf + 1) % 3;
    }
#undef LOAD_STAGE

#pragma unroll
    for (int mt = 0; mt < 4; mt++) {
#pragma unroll
        for (int half = 0; half < 2; half++) {
            int m = m0 + wm * 64 + mt * 16 + g + half * 8;
            if (m >= M) continue;
#pragma unroll
            for (int nt = 0; nt < 8; nt++) {
                int n = n0 + wn * 64 + nt * 8 + 2 * c;
                if (n >= Nc) continue;
                float v0 = acc[mt][nt][half * 2 + 0];
                float v1 = acc[mt][nt][half * 2 + 1];
                if (EPI == 1) {
                    v0 = fmaxf(v0 + bias[n], 0.f);
                    v1 = fmaxf(v1 + bias[n + 1], 0.f);
                    *(__half2*)(Ch + (long)m * ldc + n) = __floats2half2_rn(v0, v1);
                } else if (EPI == 2) {
                    v0 = v0 + bias[n] + res[(long)m * Nc + n];
                    v1 = v1 + bias[n + 1] + res[(long)m * Nc + n + 1];
                    *(float2*)(Cf + (long)m * ldc + n) = make_float2(v0, v1);
                } else if (EPI == 3) {
                    *(__half2*)(Ch + (long)m * ldc + n) = __floats2half2_rn(v0, v1);
                } else {
                    *(float2*)(Cf + (long)m * ldc + n) = make_float2(v0, v1);
                }
            }
        }
    }
}

// ---------------- P = We @ e, both layers ----------------
__global__ void p_kernel(const float* __restrict__ we, const float* __restrict__ ev) {
    int j = blockIdx.x * 8 + (threadIdx.x >> 5);
    int lane = threadIdx.x & 31;
    float a[8];
#pragma unroll
    for (int u = 0; u < 8; u++) a[u] = 0.f;
#pragma unroll
    for (int jj = 0; jj < 16; jj++) {
        int c = lane + 32 * jj;
        float w0 = we[(long)j * CV + c];
        float w1 = we[(long)EDV * CV + (long)j * CV + c];
        float4 e0 = *(const float4*)(ev + c * HV);
        float4 e1 = *(const float4*)(ev + CV * HV + c * HV);
        a[0] = fmaf(w0, e0.x, a[0]); a[1] = fmaf(w0, e0.y, a[1]);
        a[2] = fmaf(w0, e0.z, a[2]); a[3] = fmaf(w0, e0.w, a[3]);
        a[4] = fmaf(w1, e1.x, a[4]); a[5] = fmaf(w1, e1.y, a[5]);
        a[6] = fmaf(w1, e1.z, a[6]); a[7] = fmaf(w1, e1.w, a[7]);
    }
#pragma unroll
    for (int u = 0; u < 8; u++) a[u] = warp_red(a[u]);
    if (lane == 0) {
        *(float4*)(g_P + j * 8) = make_float4(a[0], a[1], a[2], a[3]);
        *(float4*)(g_P + j * 8 + 4) = make_float4(a[4], a[5], a[6], a[7]);
    }
}

// ---------------- ae = eattr @ P, both layers, written in CSR order ----------------
__global__ void ae_kernel(const float* __restrict__ eattr) {
    int e = blockIdx.x * 8 + (threadIdx.x >> 5);
    int lane = threadIdx.x & 31;
    float a[8];
#pragma unroll
    for (int u = 0; u < 8; u++) a[u] = 0.f;
#pragma unroll
    for (int jj = 0; jj < 24; jj++) {
        int j = lane + 32 * jj;
        float v = eattr[(long)e * EDV + j];
        float4 p0 = *(const float4*)(g_P + j * 8);
        float4 p1 = *(const float4*)(g_P + j * 8 + 4);
        a[0] = fmaf(v, p0.x, a[0]); a[1] = fmaf(v, p0.y, a[1]);
        a[2] = fmaf(v, p0.z, a[2]); a[3] = fmaf(v, p0.w, a[3]);
        a[4] = fmaf(v, p1.x, a[4]); a[5] = fmaf(v, p1.y, a[5]);
        a[6] = fmaf(v, p1.z, a[6]); a[7] = fmaf(v, p1.w, a[7]);
    }
#pragma unroll
    for (int u = 0; u < 8; u++) a[u] = warp_red(a[u]);
    int pos = g_epos[e];
    if (lane == 0) {
        *(float4*)(g_ae + (long)pos * 8) = make_float4(a[0], a[1], a[2], a[3]);
        *(float4*)(g_ae + (long)pos * 8 + 4) = make_float4(a[4], a[5], a[6], a[7]);
    }
}

// ==== fused softmax + CSR aggregation: per-block local denominator, no atomics ====
__global__ void agg_kernel(const float* __restrict__ xin, float* __restrict__ xout,
                           __half* __restrict__ xout_h, const float* __restrict__ bias,
                           int l) {
    int n = blockIdx.x, t = threadIdx.x;
    __shared__ float sq[64];
    __shared__ float salpha[MAXD * 4];
    __shared__ float sden[4][32];
    __shared__ float sdent[4];

    int b0 = g_off[n], deg = g_off[n + 1] - b0;
    if (t < 64) sq[t] = g_QK[(long)n * 64 + t];
    __syncthreads();

    // pass 1: logits -> exp, cache in smem, accumulate denominator
    int h1 = t & 3, el = t >> 2;   // 32 edges x 4 heads per sweep
    bool cached = (deg <= MAXD);
    float pden = 0.f;
    for (int base = 0; base < deg; base += 32) {
        int ii = base + el;
        if (ii < deg) {
            int gi = g_gidx[b0 + ii];
            int src = gi >> 3, ty = gi & 7;
            float ae = g_ae[(long)(b0 + ii) * 8 + l * 4 + h1];
            float qv = sq[ty * 4 + h1];
            float kv = g_QK[(long)src * 64 + 32 + ty * 4 + h1];
            float a = qv + kv + ae;
            a = a > 0.f ? a : 0.2f * a;
            a = expf(a);
            if (cached) salpha[ii * 4 + h1] = a;
            pden += a;
        }
    }
    sden[h1][el] = pden;
    __syncthreads();
    if (t < 4) {
        float s = 0.f;
#pragma unroll
        for (int i = 0; i < 32; i++) s += sden[t][i];
        sdent[t] = s;
    }
    __syncthreads();

    // pass 2: normalize + gather-accumulate (4 channels per thread)
    int h2 = t >> 5;
    float inv = 1.f / (sdent[h2] + 1e-16f);
    float4 acc = ((const float4*)bias)[t];
    float4 xr = ((const float4*)(xin + (long)n * CV))[t];
    acc.x += xr.x; acc.y += xr.y; acc.z += xr.z; acc.w += xr.w;

    if (cached) {
        int ii = 0;
        for (; ii + 4 <= deg; ii += 4) {
            int gi0 = g_gidx[b0 + ii + 0];
            int gi1 = g_gidx[b0 + ii + 1];
            int gi2 = g_gidx[b0 + ii + 2];
            int gi3 = g_gidx[b0 + ii + 3];
            float c0 = salpha[(ii + 0) * 4 + h2] * inv;
            float c1 = salpha[(ii + 1) * 4 + h2] * inv;
            float c2 = salpha[(ii + 2) * 4 + h2] * inv;
            float c3 = salpha[(ii + 3) * 4 + h2] * inv;
            uint2 u0 = *(const uint2*)(g_xwh + (long)gi0 * CV + t * 4);
            uint2 u1 = *(const uint2*)(g_xwh + (long)gi1 * CV + t * 4);
            uint2 u2 = *(const uint2*)(g_xwh + (long)gi2 * CV + t * 4);
            uint2 u3 = *(const uint2*)(g_xwh + (long)gi3 * CV + t * 4);
            float2 a01, a23;
            a01 = __half22float2(*(__half2*)&u0.x); a23 = __half22float2(*(__half2*)&u0.y);
            acc.x = fmaf(c0, a01.x, acc.x); acc.y = fmaf(c0, a01.y, acc.y);
            acc.z = fmaf(c0, a23.x, acc.z); acc.w = fmaf(c0, a23.y, acc.w);
            a01 = __half22float2(*(__half2*)&u1.x); a23 = __half22float2(*(__half2*)&u1.y);
            acc.x = fmaf(c1, a01.x, acc.x); acc.y = fmaf(c1, a01.y, acc.y);
            acc.z = fmaf(c1, a23.x, acc.z); acc.w = fmaf(c1, a23.y, acc.w);
            a01 = __half22float2(*(__half2*)&u2.x); a23 = __half22float2(*(__half2*)&u2.y);
            acc.x = fmaf(c2, a01.x, acc.x); acc.y = fmaf(c2, a01.y, acc.y);
            acc.z = fmaf(c2, a23.x, acc.z); acc.w = fmaf(c2, a23.y, acc.w);
            a01 = __half22float2(*(__half2*)&u3.x); a23 = __half22float2(*(__half2*)&u3.y);
            acc.x = fmaf(c3, a01.x, acc.x); acc.y = fmaf(c3, a01.y, acc.y);
            acc.z = fmaf(c3, a23.x, acc.z); acc.w = fmaf(c3, a23.y, acc.w);
        }
        for (; ii < deg; ii++) {
            int gi = g_gidx[b0 + ii];
            float cf = salpha[ii * 4 + h2] * inv;
            uint2 u = *(const uint2*)(g_xwh + (long)gi * CV + t * 4);
            float2 a01 = __half22float2(*(__half2*)&u.x);
            float2 a23 = __half22float2(*(__half2*)&u.y);
            acc.x = fmaf(cf, a01.x, acc.x); acc.y = fmaf(cf, a01.y, acc.y);
            acc.z = fmaf(cf, a23.x, acc.z); acc.w = fmaf(cf, a23.y, acc.w);
        }
    } else {
        // exact fallback for pathological degrees: recompute alpha inline
        for (int ii = 0; ii < deg; ii++) {
            int gi = g_gidx[b0 + ii];
            int src = gi >> 3, ty = gi & 7;
            float ae = g_ae[(long)(b0 + ii) * 8 + l * 4 + h2];
            float qv = sq[ty * 4 + h2];
            float kv = g_QK[(long)src * 64 + 32 + ty * 4 + h2];
            float a = qv + kv + ae;
            a = a > 0.f ? a : 0.2f * a;
            float cf = expf(a) * inv;
            uint2 u = *(const uint2*)(g_xwh + (long)gi * CV + t * 4);
            float2 a01 = __half22float2(*(__half2*)&u.x);
            float2 a23 = __half22float2(*(__half2*)&u.y);
            acc.x = fmaf(cf, a01.x, acc.x); acc.y = fmaf(cf, a01.y, acc.y);
            acc.z = fmaf(cf, a23.x, acc.z); acc.w = fmaf(cf, a23.y, acc.w);
        }
    }

    ((float4*)(xout + (long)n * CV))[t] = acc;
    if (xout_h) {
        ((__half2*)(xout_h + (long)n * CV))[t * 2 + 0] = __floats2half2_rn(acc.x, acc.y);
        ((__half2*)(xout_h + (long)n * CV))[t * 2 + 1] = __floats2half2_rn(acc.z, acc.w);
    }
}

// ---------------- layernorm (optionally emits fp16 copy) ----------------
__global__ void ln_kernel(const float* __restrict__ in, const float* __restrict__ addpre,
                          const float* __restrict__ addpost, float* __restrict__ out,
                          __half* __restrict__ out_h,
                          const float* __restrict__ gamma, const float* __restrict__ beta) {
    int n = blockIdx.x, t = threadIdx.x;
    int lane = t & 31, w = t >> 5;
    __shared__ float sred[4];
    float4 x = ((const float4*)(in + (long)n * CV))[t];
    if (addpre) {
        float4 a = ((const float4*)(addpre + (long)n * CV))[t];
        x.x += a.x; x.y += a.y; x.z += a.z; x.w += a.w;
    }
    float s = x.x + x.y + x.z + x.w;
    s = warp_red(s);
    if (!lane) sred[w] = s;
    __syncthreads();
    float mean = (sred[0] + sred[1] + sred[2] + sred[3]) * (1.f / CV);
    __syncthreads();
    float dx = x.x - mean, dy = x.y - mean, dz = x.z - mean, dw = x.w - mean;
    float ss = dx * dx + dy * dy + dz * dz + dw * dw;
    ss = warp_red(ss);
    if (!lane) sred[w] = ss;
    __syncthreads();
    float var = (sred[0] + sred[1] + sred[2] + sred[3]) * (1.f / CV);
    float rstd = rsqrtf(var + 1e-5f);
    float4 g = ((const float4*)gamma)[t];
    float4 b = ((const float4*)beta)[t];
    float4 o;
    o.x = g.x * dx * rstd + b.x;
    o.y = g.y * dy * rstd + b.y;
    o.z = g.z * dz * rstd + b.z;
    o.w = g.w * dw * rstd + b.w;
    if (addpost) {
        float4 p = ((const float4*)(addpost + (long)n * CV))[t];
        o.x += p.x; o.y += p.y; o.z += p.z; o.w += p.w;
    }
    ((float4*)(out + (long)n * CV))[t] = o;
    if (out_h) {
        ((__half2*)(out_h + (long)n * CV))[t * 2 + 0] = __floats2half2_rn(o.x, o.y);
        ((__half2*)(out_h + (long)n * CV))[t * 2 + 1] = __floats2half2_rn(o.z, o.w);
    }
}

// ---------------- launcher ----------------
extern "C" void kernel_launch(void* const* d_in, const int* in_sizes, int n_in,
                              void* d_out, int out_size) {
    const float* x   = (const float*)d_in[0];
    const void*  ei  = d_in[1];
    const void*  et  = d_in[2];
    const float* eattr = (const float*)d_in[3];
    const float* W   = (const float*)d_in[4];
    const float* qm  = (const float*)d_in[5];
    const float* km  = (const float*)d_in[6];
    const float* em  = (const float*)d_in[7];
    const float* we  = (const float*)d_in[8];
    const float* cb  = (const float*)d_in[9];
    const float* lg  = (const float*)d_in[10];
    const float* lb  = (const float*)d_in[11];
    const float* f1w = (const float*)d_in[12];
    const float* f1b = (const float*)d_in[13];
    const float* f2w = (const float*)d_in[14];
    const float* f2b = (const float*)d_in[15];
    float* out = (float*)d_out;

    float *pxA, *pxB, *ph0, *pQK;
    __half *pxwh, *pxh, *ph0h, *ph1h, *pWth, *pf1th, *pf2th, *pWqkh;
    cudaGetSymbolAddress((void**)&pxwh, g_xwh);
    cudaGetSymbolAddress((void**)&pxA, g_xA);
    cudaGetSymbolAddress((void**)&pxB, g_xB);
    cudaGetSymbolAddress((void**)&ph0, g_h0);
    cudaGetSymbolAddress((void**)&pQK, g_QK);
    cudaGetSymbolAddress((void**)&pxh, g_xh);
    cudaGetSymbolAddress((void**)&ph0h, g_h0h);
    cudaGetSymbolAddress((void**)&ph1h, g_h1h);
    cudaGetSymbolAddress((void**)&pWth, g_Wth);
    cudaGetSymbolAddress((void**)&pf1th, g_f1th);
    cudaGetSymbolAddress((void**)&pf2th, g_f2th);
    cudaGetSymbolAddress((void**)&pWqkh, g_Wqkh);

    cudaFuncSetAttribute(hgemm_k<0>, cudaFuncAttributeMaxDynamicSharedMemorySize, HG_SMEM);
    cudaFuncSetAttribute(hgemm_k<1>, cudaFuncAttributeMaxDynamicSharedMemorySize, HG_SMEM);
    cudaFuncSetAttribute(hgemm_k<2>, cudaFuncAttributeMaxDynamicSharedMemorySize, HG_SMEM);
    cudaFuncSetAttribute(hgemm_k<3>, cudaFuncAttributeMaxDynamicSharedMemorySize, HG_SMEM);

    const int TB = 256;
    const int EB = (EV + TB - 1) / TB;
    const int MT = (NV + 127) / 128;

    detect_kernel<<<1, 256>>>((const int*)ei, (const int*)et);
    convert_kernel<<<EB, TB>>>(ei, et);
    reset_cnt_kernel<<<(NV + TB - 1) / TB, TB>>>();
    hist_kernel<<<EB, TB>>>();
    scan_kernel<<<1, 1024>>>();
    scatter_kernel<<<EB, TB>>>();

    // edge-attr projections for BOTH layers in one eattr pass (CSR-ordered output)
    p_kernel<<<EDV / 8, 256>>>(we, em);
    ae_kernel<<<EV / 8, 256>>>(eattr);

    // fused QK weights + transposed fp16 weight copies
    wqk_kernel<<<LLV * RV, 256>>>(W, qm, km);
    {
        dim3 tb(32, 8);
        dim3 gw(CV / 32, CV / 32, LLV * RV);
        trans_cvt_kernel<<<gw, tb>>>(W, pWth, CV, CV);
        dim3 g1(2 * CV / 32, CV / 32, 1);
        trans_cvt_kernel<<<g1, tb>>>(f1w, pf1th, CV, 2 * CV);
        dim3 g2(CV / 32, 2 * CV / 32, 1);
        trans_cvt_kernel<<<g2, tb>>>(f2w, pf2th, 2 * CV, CV);
    }

    // fp16 copy of layer-0 activations
    cvt_half_kernel<<<(NV * CV / 4 + TB - 1) / TB, TB>>>(x, pxh, NV * CV / 4);

    for (int l = 0; l < LLV; l++) {
        const float* xin = (l == 0) ? x : pxB;
        float* xout = (l == 0) ? pxB : pxA;
        __half* xout_h = (l == 0) ? pxh : nullptr;

        // xwh[n,r,:] = xh @ Wth[l,r]^T  (fp16 out, L2-resident gather source)
        dim3 g1(CV / 128, MT, RV);
        hgemm_k<3><<<g1, 128, HG_SMEM>>>(pxh, pWth + (long)l * RV * CV * CV, pxwh,
                                         NV, CV, CV, CV, CV, RV * CV,
                                         (long)CV * CV, (long)CV, nullptr, nullptr);

        // QK[n, 0..63] = xh @ Wqkh[l]^T
        dim3 gq(1, MT, 1);
        hgemm_k<0><<<gq, 128, HG_SMEM>>>(pxh, pWqkh + (long)l * 64 * CV, pQK,
                                         NV, 64, CV, CV, CV, 64, 0, 0, nullptr, nullptr);

        // fused softmax + aggregation
        agg_kernel<<<NV, 128>>>(xin, xout, xout_h, cb + l * CV, l);
    }

    // h0 = LN(xA + enc_emb), also emit fp16 copy
    ln_kernel<<<NV, 128>>>(pxA, x, nullptr, ph0, ph0h, lg, lb);
    // h1h = half(relu(h0h @ f1th^T + b1))
    {
        dim3 g2(2 * CV / 128, MT, 1);
        hgemm_k<1><<<g2, 128, HG_SMEM>>>(ph0h, pf1th, ph1h, NV, 2 * CV, CV,
                                         CV, CV, 2 * CV, 0, 0, f1b, nullptr);
    }
    // h2 = h1h @ f2th^T + b2 + h0  (into pxB)
    {
        dim3 g3(CV / 128, MT, 1);
        hgemm_k<2><<<g3, 128, HG_SMEM>>>(ph1h, pf2th, pxB, NV, CV, 2 * CV,
                                         2 * CV, 2 * CV, CV, 0, 0, f2b, ph0);
    }
    // out = LN(h2) + enc_emb
    ln_kernel<<<NV, 128>>>(pxB, nullptr, x, out, nullptr, lg, lb);
}